// round 11
// baseline (speedup 1.0000x reference)
#include <cuda_runtime.h>
#include <cuda_fp16.h>
#include <cstdint>
#include <cstddef>

#define Nn 50000
#define Ee 800000

// ---------------- scratch (static device globals; no allocation) ----------------
// float accumulators (permuted channel layout p(c)=16t+2nt+j for c=8nt+2t+j)
__device__ float4 g_s4  [Nn * 16];
__device__ float4 g_acc4[Nn * 16];
// fp16 node operands, permuted layout: v, Q=h@(Wsrc*Wa1), P=h@(Wdst*Wa1)
__device__ __align__(16) __half g_vh[Nn * 64];
__device__ __align__(16) __half g_Qh[Nn * 64];
__device__ __align__(16) __half g_Ph[Nn * 64];
// folded weights (fp32, row-major 64x64) + folded bias
__device__ float g_WsA[4096];
__device__ float g_WdA[4096];
__device__ float g_WpA[4096];
__device__ float g_cvec[64];

// ---------------- helpers ----------------
__device__ __forceinline__ uint32_t pack_f16x2(float a, float b) {
    uint32_t w;
    asm("cvt.rn.f16x2.f32 %0, %1, %2;" : "=r"(w) : "f"(b), "f"(a));  // lo=a, hi=b
    return w;
}
__device__ __forceinline__ void pack_hl_f16(float a, float b, uint32_t& h, uint32_t& l) {
    asm("cvt.rn.f16x2.f32 %0, %1, %2;" : "=r"(h) : "f"(b), "f"(a));
    __half2 h2 = *reinterpret_cast<__half2*>(&h);
    float la = a - __half2float(h2.x);
    float lb = b - __half2float(h2.y);
    asm("cvt.rn.f16x2.f32 %0, %1, %2;" : "=r"(l) : "f"(lb), "f"(la));
}
__device__ __forceinline__ float2 h2f2(uint32_t w) {
    __half2 h = *reinterpret_cast<__half2*>(&w);
    return make_float2(__half2float(h.x), __half2float(h.y));
}
__device__ __forceinline__ void red4(float4* p, float a, float b, float c, float d) {
    asm volatile("red.global.add.v4.f32 [%0], {%1, %2, %3, %4};"
                 :: "l"(p), "f"(a), "f"(b), "f"(c), "f"(d) : "memory");
}
__device__ __forceinline__ void mma_f16(float* d, const uint32_t* a, uint32_t b0, uint32_t b1) {
    asm volatile(
        "mma.sync.aligned.m16n8k16.row.col.f32.f16.f16.f32 "
        "{%0,%1,%2,%3},{%4,%5,%6,%7},{%8,%9},{%0,%1,%2,%3};"
        : "+f"(d[0]), "+f"(d[1]), "+f"(d[2]), "+f"(d[3])
        : "r"(a[0]), "r"(a[1]), "r"(a[2]), "r"(a[3]), "r"(b0), "r"(b1));
}

// GEMM with uint4-packed B (one LDS.128 feeds two mmas)
__device__ __forceinline__ void gemm1p(float* D, const uint32_t* Ah,
                                       const uint4* __restrict__ bf, int lane) {
#pragma unroll
    for (int kt = 0; kt < 4; kt++)
#pragma unroll
        for (int ntp = 0; ntp < 4; ntp++) {
            uint4 b = bf[(kt * 4 + ntp) * 32 + lane];
            mma_f16(D + (2 * ntp)     * 4, Ah + kt * 4, b.x, b.y);
            mma_f16(D + (2 * ntp + 1) * 4, Ah + kt * 4, b.z, b.w);
        }
}
__device__ __forceinline__ void gemm2p(float* D, const uint32_t* Ah,
                                       const uint4* __restrict__ bfH,
                                       const uint4* __restrict__ bfL, int lane) {
#pragma unroll
    for (int kt = 0; kt < 4; kt++)
#pragma unroll
        for (int ntp = 0; ntp < 4; ntp++) {
            uint4 bh = bfH[(kt * 4 + ntp) * 32 + lane];
            mma_f16(D + (2 * ntp)     * 4, Ah + kt * 4, bh.x, bh.y);
            mma_f16(D + (2 * ntp + 1) * 4, Ah + kt * 4, bh.z, bh.w);
            uint4 bl = bfL[(kt * 4 + ntp) * 32 + lane];
            mma_f16(D + (2 * ntp)     * 4, Ah + kt * 4, bl.x, bl.y);
            mma_f16(D + (2 * ntp + 1) * 4, Ah + kt * 4, bl.z, bl.w);
        }
}
__device__ __forceinline__ void gemm3p(float* D, const uint32_t* Ah, const uint32_t* Al,
                                       const uint4* __restrict__ bfH,
                                       const uint4* __restrict__ bfL, int lane) {
#pragma unroll
    for (int kt = 0; kt < 4; kt++)
#pragma unroll
        for (int ntp = 0; ntp < 4; ntp++) {
            uint4 bh = bfH[(kt * 4 + ntp) * 32 + lane];
            mma_f16(D + (2 * ntp)     * 4, Ah + kt * 4, bh.x, bh.y);
            mma_f16(D + (2 * ntp + 1) * 4, Ah + kt * 4, bh.z, bh.w);
            mma_f16(D + (2 * ntp)     * 4, Al + kt * 4, bh.x, bh.y);
            mma_f16(D + (2 * ntp + 1) * 4, Al + kt * 4, bh.z, bh.w);
            uint4 bl = bfL[(kt * 4 + ntp) * 32 + lane];
            mma_f16(D + (2 * ntp)     * 4, Ah + kt * 4, bl.x, bl.y);
            mma_f16(D + (2 * ntp + 1) * 4, Ah + kt * 4, bl.z, bl.w);
        }
}

// build uint4-packed B fragments from 64x64 row-major W; dstL may be null.
// fragment (kt,nt) for lane -> uint4 slot (kt*4 + nt/2)*32 + lane, halves by nt&1
__device__ __forceinline__ void build_bf4(uint4* dstH, uint4* dstL,
                                          const float* __restrict__ W,
                                          int tid, int nth) {
    for (int i = tid; i < 1024; i += nth) {
        int kt = i >> 8, nt = (i >> 5) & 7, lane = i & 31;
        int g = lane >> 2, t = lane & 3;
        int col = 8 * nt + g;
        int k0  = 16 * kt + 2 * t;
        float w00 = W[(k0    ) * 64 + col];
        float w01 = W[(k0 + 1) * 64 + col];
        float w10 = W[(k0 + 8) * 64 + col];
        float w11 = W[(k0 + 9) * 64 + col];
        uint32_t h0, l0, h1, l1;
        pack_hl_f16(w00, w01, h0, l0);
        pack_hl_f16(w10, w11, h1, l1);
        uint32_t* pH = (uint32_t*)&dstH[(kt * 4 + (nt >> 1)) * 32 + lane];
        int sub = (nt & 1) * 2;
        pH[sub] = h0; pH[sub + 1] = h1;
        if (dstL) {
            uint32_t* pL = (uint32_t*)&dstL[(kt * 4 + (nt >> 1)) * 32 + lane];
            pL[sub] = l0; pL[sub + 1] = l1;
        }
    }
}

// ---------------- kernel -1: fold weight products (fp32) ----------------
__global__ __launch_bounds__(256) void fold_kernel(
    const float* __restrict__ Wsrc, const float* __restrict__ Wdst,
    const float* __restrict__ Wp2,  const float* __restrict__ Wa1,
    const float* __restrict__ bp2,  const float* __restrict__ ba1)
{
    int gid = blockIdx.x * blockDim.x + threadIdx.x;
    if (gid < 3 * 4096) {
        int m = gid >> 12;
        int idx = gid & 4095;
        int i = idx >> 6, j = idx & 63;
        const float* A = (m == 0) ? Wsrc : (m == 1) ? Wdst : Wp2;
        float s = 0.f;
        for (int k = 0; k < 64; k++) s = fmaf(A[i * 64 + k], Wa1[k * 64 + j], s);
        float* O = (m == 0) ? g_WsA : (m == 1) ? g_WdA : g_WpA;
        O[idx] = s;
    }
    if (gid < 64) {
        float s = ba1[gid];
        for (int k = 0; k < 64; k++) s = fmaf(bp2[k], Wa1[k * 64 + gid], s);
        g_cvec[gid] = s;
    }
}

// ---------------- kernel 0: init reduction buffers ----------------
__global__ __launch_bounds__(256) void init_kernel() {
    int i = blockIdx.x * blockDim.x + threadIdx.x;
    if (i < Nn * 16) {
        g_s4[i]   = make_float4(0.f, 0.f, 0.f, 0.f);
        g_acc4[i] = make_float4(0.f, 0.f, 0.f, 0.f);
    }
}

// ---------------- kernel 1: node projections (mma; outputs v, Q, P fp16 permuted) ----------------
__global__ __launch_bounds__(256) void node_proj_kernel(
    const float* __restrict__ x,
    const float* __restrict__ Win,  const float* __restrict__ bin,
    const float* __restrict__ Wlin)
{
    extern __shared__ __align__(16) char smem[];
    uint4*  sBF  = (uint4*)smem;                       // 8 x 512 uint4 = 64KB
    float2* sBin = (float2*)(smem + 65536);
    const int tid = threadIdx.x;

    build_bf4(sBF + 0 * 512, sBF + 1 * 512, Win,  tid, 256);
    build_bf4(sBF + 2 * 512, sBF + 3 * 512, Wlin, tid, 256);
    build_bf4(sBF + 4 * 512, sBF + 5 * 512, (const float*)g_WsA, tid, 256);
    build_bf4(sBF + 6 * 512, sBF + 7 * 512, (const float*)g_WdA, tid, 256);
    if (tid < 32) sBin[tid] = make_float2(bin[2 * tid], bin[2 * tid + 1]);
    __syncthreads();

    const int lane = tid & 31;
    const int g = lane >> 2, t = lane & 3;

    __half* outs[3] = { g_vh, g_Qh, g_Ph };

    const int nTiles = Nn / 16;  // 3125
    const int wStride = gridDim.x * 8;
    for (int tile = blockIdx.x * 8 + (tid >> 5); tile < nTiles; tile += wStride) {
        const int n0 = tile * 16;

        uint32_t Ah[16];
#pragma unroll
        for (int kt = 0; kt < 4; kt++)
#pragma unroll
            for (int half = 0; half < 2; half++)
#pragma unroll
                for (int h = 0; h < 2; h++) {
                    float2 xx = *(const float2*)&x[(n0 + g + 8 * h) * 64 + 16 * kt + 2 * t + 8 * half];
                    Ah[kt * 4 + h + 2 * half] = pack_f16x2(xx.x, xx.y);
                }

        float D[32];
#pragma unroll
        for (int i = 0; i < 32; i++) D[i] = 0.f;
        gemm2p(D, Ah, sBF + 0 * 512, sBF + 1 * 512, lane);

        uint32_t Ah2[16];
#pragma unroll
        for (int nt = 0; nt < 8; nt++) {
            float2 bb = sBin[4 * nt + t];
            int kt = nt >> 1, half = nt & 1, slot = kt * 4 + 2 * half;
            Ah2[slot]     = pack_f16x2(fmaxf(D[nt * 4 + 0] + bb.x, 0.f),
                                       fmaxf(D[nt * 4 + 1] + bb.y, 0.f));
            Ah2[slot + 1] = pack_f16x2(fmaxf(D[nt * 4 + 2] + bb.x, 0.f),
                                       fmaxf(D[nt * 4 + 3] + bb.y, 0.f));
        }

#pragma unroll
        for (int m = 0; m < 3; m++) {
#pragma unroll
            for (int i = 0; i < 32; i++) D[i] = 0.f;
            gemm2p(D, Ah2, sBF + (2 + 2 * m) * 512, sBF + (3 + 2 * m) * 512, lane);
            __half* o = outs[m];
#pragma unroll
            for (int ntp = 0; ntp < 4; ntp++) {
                int na = 2 * ntp, nb = na + 1;
                uint2 r0 = make_uint2(pack_f16x2(D[na * 4 + 0], D[na * 4 + 1]),
                                      pack_f16x2(D[nb * 4 + 0], D[nb * 4 + 1]));
                uint2 r8 = make_uint2(pack_f16x2(D[na * 4 + 2], D[na * 4 + 3]),
                                      pack_f16x2(D[nb * 4 + 2], D[nb * 4 + 3]));
                *(uint2*)(o + (n0 + g    ) * 64 + 16 * t + 4 * ntp) = r0;
                *(uint2*)(o + (n0 + g + 8) * 64 + 16 * t + 4 * ntp) = r8;
            }
        }
    }
}

// ---------------- kernel 2: fused edge kernel (folded path, uint4 B frags) ----------------
#define ESM_WP1   24576
#define ESM_BP2   25600
#define ESM_CV    25856
#define ESM_BA2   26112
#define ESM_TOTAL 26624

__global__ __launch_bounds__(256, 2) void edge_fused_kernel(
    const float* __restrict__ pos, const int* __restrict__ ei,
    const float* __restrict__ Wp1, const float* __restrict__ bp1,
    const float* __restrict__ Wp2, const float* __restrict__ bp2,
    const float* __restrict__ Wa2, const float* __restrict__ ba2)
{
    extern __shared__ __align__(16) char smem[];
    uint4*  sBF  = (uint4*)smem;
    float4* sWp1 = (float4*)(smem + ESM_WP1);
    float2* sBp2 = (float2*)(smem + ESM_BP2);
    float2* sCv  = (float2*)(smem + ESM_CV);
    float2* sBa2 = (float2*)(smem + ESM_BA2);

    const int tid = threadIdx.x;
    build_bf4(sBF + 0 * 512, (uint4*)0, Wp2,                 tid, 256);
    build_bf4(sBF + 1 * 512, (uint4*)0, (const float*)g_WpA, tid, 256);
    build_bf4(sBF + 2 * 512, (uint4*)0, Wa2,                 tid, 256);
    if (tid < 64)
        sWp1[tid] = make_float4(Wp1[tid], Wp1[64 + tid], Wp1[128 + tid], bp1[tid]);
    if (tid < 32) {
        sBp2[tid] = make_float2(bp2[2 * tid], bp2[2 * tid + 1]);
        sCv[tid]  = make_float2(g_cvec[2 * tid], g_cvec[2 * tid + 1]);
        sBa2[tid] = make_float2(ba2[2 * tid], ba2[2 * tid + 1]);
    }
    __syncthreads();

    const int lane = tid & 31;
    const int g = lane >> 2, t = lane & 3;

    const uint4* bfP2h = sBF + 0 * 512;
    const uint4* bfPAh = sBF + 1 * 512;
    const uint4* bfA2h = sBF + 2 * 512;

    const int nTiles = Ee / 16;          // 50000
    const int wStride = gridDim.x * 8;

    int tile = blockIdx.x * 8 + (tid >> 5);

    int pS = 0, pD = 0;
    float pr0 = 0.f, pr1 = 0.f, pr2 = 0.f;
    if (tile < nTiles && lane < 16) {
        int e = tile * 16 + lane;
        pS = __ldg(&ei[e]);
        pD = __ldg(&ei[Ee + e]);
        pr0 = __ldg(&pos[pD * 3 + 0]) - __ldg(&pos[pS * 3 + 0]);
        pr1 = __ldg(&pos[pD * 3 + 1]) - __ldg(&pos[pS * 3 + 1]);
        pr2 = __ldg(&pos[pD * 3 + 2]) - __ldg(&pos[pS * 3 + 2]);
    }

    for (; tile < nTiles; tile += wStride) {
        int sn[2], dn[2];
        float rl[2][3];
#pragma unroll
        for (int h = 0; h < 2; h++) {
            int src = g + 8 * h;
            sn[h]   = __shfl_sync(0xffffffffu, pS, src);
            dn[h]   = __shfl_sync(0xffffffffu, pD, src);
            rl[h][0] = __shfl_sync(0xffffffffu, pr0, src);
            rl[h][1] = __shfl_sync(0xffffffffu, pr1, src);
            rl[h][2] = __shfl_sync(0xffffffffu, pr2, src);
        }

        const int tn = tile + wStride;
        int nS = 0, nD = 0;
        if (tn < nTiles && lane < 16) {
            int e = tn * 16 + lane;
            nS = __ldg(&ei[e]);
            nD = __ldg(&ei[Ee + e]);
        }

        // hoist P/Q gathers (consumed after G2')
        uint4 P0a = __ldg((const uint4*)(g_Ph + dn[0] * 64 + 16 * t));
        uint4 P0b = __ldg((const uint4*)(g_Ph + dn[0] * 64 + 16 * t + 8));
        uint4 Q0a = __ldg((const uint4*)(g_Qh + sn[0] * 64 + 16 * t));
        uint4 Q0b = __ldg((const uint4*)(g_Qh + sn[0] * 64 + 16 * t + 8));
        uint4 P1a = __ldg((const uint4*)(g_Ph + dn[1] * 64 + 16 * t));
        uint4 P1b = __ldg((const uint4*)(g_Ph + dn[1] * 64 + 16 * t + 8));
        uint4 Q1a = __ldg((const uint4*)(g_Qh + sn[1] * 64 + 16 * t));
        uint4 Q1b = __ldg((const uint4*)(g_Qh + sn[1] * 64 + 16 * t + 8));

        // stage 1: u = relu(rel @ Wp1 + bp1) -> A frags
        uint32_t Au[16];
#pragma unroll
        for (int kt = 0; kt < 4; kt++)
#pragma unroll
            for (int half = 0; half < 2; half++) {
                int c0 = 16 * kt + 2 * t + 8 * half;
                float4 w0 = sWp1[c0];
                float4 w1 = sWp1[c0 + 1];
#pragma unroll
                for (int h = 0; h < 2; h++) {
                    float u0 = fmaxf(fmaf(rl[h][2], w0.z, fmaf(rl[h][1], w0.y,
                               fmaf(rl[h][0], w0.x, w0.w))), 0.f);
                    float u1 = fmaxf(fmaf(rl[h][2], w1.z, fmaf(rl[h][1], w1.y,
                               fmaf(rl[h][0], w1.x, w1.w))), 0.f);
                    Au[kt * 4 + h + 2 * half] = pack_f16x2(u0, u1);
                }
            }

        // G2': h2_pre = u @ WpA
        float Dx[32];
#pragma unroll
        for (int i = 0; i < 32; i++) Dx[i] = 0.f;
        gemm1p(Dx, Au, bfPAh, lane);

        if (tn < nTiles && lane < 16) {
            pr0 = __ldg(&pos[nD * 3 + 0]) - __ldg(&pos[nS * 3 + 0]);
            pr1 = __ldg(&pos[nD * 3 + 1]) - __ldg(&pos[nS * 3 + 1]);
            pr2 = __ldg(&pos[nD * 3 + 2]) - __ldg(&pos[nS * 3 + 2]);
        }
        pS = nS; pD = nD;

        // epi-a: Dx += cvec + P[dn] - Q[sn]
        {
            uint32_t wP0[8] = {P0a.x, P0a.y, P0a.z, P0a.w, P0b.x, P0b.y, P0b.z, P0b.w};
            uint32_t wQ0[8] = {Q0a.x, Q0a.y, Q0a.z, Q0a.w, Q0b.x, Q0b.y, Q0b.z, Q0b.w};
            uint32_t wP1[8] = {P1a.x, P1a.y, P1a.z, P1a.w, P1b.x, P1b.y, P1b.z, P1b.w};
            uint32_t wQ1[8] = {Q1a.x, Q1a.y, Q1a.z, Q1a.w, Q1b.x, Q1b.y, Q1b.z, Q1b.w};
#pragma unroll
            for (int nt = 0; nt < 8; nt++) {
                float2 cv = sCv[4 * nt + t];
                float2 p0 = h2f2(wP0[nt]), q0 = h2f2(wQ0[nt]);
                float2 p1 = h2f2(wP1[nt]), q1 = h2f2(wQ1[nt]);
                Dx[nt * 4 + 0] += cv.x + p0.x - q0.x;
                Dx[nt * 4 + 1] += cv.y + p0.y - q0.y;
                Dx[nt * 4 + 2] += cv.x + p1.x - q1.x;
                Dx[nt * 4 + 3] += cv.y + p1.y - q1.y;
            }
        }

        // G1: delta_raw = u @ Wp2 (latency filler)
        float D1[32];
#pragma unroll
        for (int i = 0; i < 32; i++) D1[i] = 0.f;
        gemm1p(D1, Au, bfP2h, lane);

        uint32_t dltp[16];
#pragma unroll
        for (int nt = 0; nt < 8; nt++) {
            float2 bb = sBp2[4 * nt + t];
            dltp[2 * nt]     = pack_f16x2(D1[nt * 4 + 0] + bb.x, D1[nt * 4 + 1] + bb.y);
            dltp[2 * nt + 1] = pack_f16x2(D1[nt * 4 + 2] + bb.x, D1[nt * 4 + 3] + bb.y);
        }

        // epi-b: h2 = relu(Dx) -> A frags
#pragma unroll
        for (int nt = 0; nt < 8; nt++) {
            int kt = nt >> 1, half = nt & 1, slot = kt * 4 + 2 * half;
            Au[slot]     = pack_f16x2(fmaxf(Dx[nt * 4 + 0], 0.f), fmaxf(Dx[nt * 4 + 1], 0.f));
            Au[slot + 1] = pack_f16x2(fmaxf(Dx[nt * 4 + 2], 0.f), fmaxf(Dx[nt * 4 + 3], 0.f));
        }

        // v gathers (covered by G3)
        uint4 v0a = __ldg((const uint4*)(g_vh + sn[0] * 64 + 16 * t));
        uint4 v0b = __ldg((const uint4*)(g_vh + sn[0] * 64 + 16 * t + 8));
        uint4 v1a = __ldg((const uint4*)(g_vh + sn[1] * 64 + 16 * t));
        uint4 v1b = __ldg((const uint4*)(g_vh + sn[1] * 64 + 16 * t + 8));

        // G3: logits = h2 @ Wa2
#pragma unroll
        for (int i = 0; i < 32; i++) Dx[i] = 0.f;
        gemm1p(Dx, Au, bfA2h, lane);

        // final epi: e = exp(Dx + ba2); scatter-add s and e*(v + delta)
        uint32_t wv0[8] = {v0a.x, v0a.y, v0a.z, v0a.w, v0b.x, v0b.y, v0b.z, v0b.w};
        uint32_t wv1[8] = {v1a.x, v1a.y, v1a.z, v1a.w, v1b.x, v1b.y, v1b.z, v1b.w};
        float* sp = (float*)g_s4;
        float* ap = (float*)g_acc4;
#pragma unroll
        for (int ntp = 0; ntp < 4; ntp++) {
            int na = 2 * ntp, nb = na + 1;
            float2 ba_a = sBa2[4 * na + t], ba_b = sBa2[4 * nb + t];
            float2 va0 = h2f2(wv0[na]), vb0 = h2f2(wv0[nb]);
            float2 va1 = h2f2(wv1[na]), vb1 = h2f2(wv1[nb]);
            float2 dna0 = h2f2(dltp[2 * na]),     dnb0 = h2f2(dltp[2 * nb]);
            float2 dna1 = h2f2(dltp[2 * na + 1]), dnb1 = h2f2(dltp[2 * nb + 1]);
            float e00 = __expf(Dx[na * 4 + 0] + ba_a.x);
            float e01 = __expf(Dx[na * 4 + 1] + ba_a.y);
            float e02 = __expf(Dx[nb * 4 + 0] + ba_b.x);
            float e03 = __expf(Dx[nb * 4 + 1] + ba_b.y);
            float a00 = e00 * (va0.x + dna0.x);
            float a01 = e01 * (va0.y + dna0.y);
            float a02 = e02 * (vb0.x + dnb0.x);
            float a03 = e03 * (vb0.y + dnb0.y);
            int off0 = dn[0] * 64 + 16 * t + 4 * ntp;
            red4((float4*)(sp + off0), e00, e01, e02, e03);
            red4((float4*)(ap + off0), a00, a01, a02, a03);
            float e10 = __expf(Dx[na * 4 + 2] + ba_a.x);
            float e11 = __expf(Dx[na * 4 + 3] + ba_a.y);
            float e12 = __expf(Dx[nb * 4 + 2] + ba_b.x);
            float e13 = __expf(Dx[nb * 4 + 3] + ba_b.y);
            float a10 = e10 * (va1.x + dna1.x);
            float a11 = e11 * (va1.y + dna1.y);
            float a12 = e12 * (vb1.x + dnb1.x);
            float a13 = e13 * (vb1.y + dnb1.y);
            int off1 = dn[1] * 64 + 16 * t + 4 * ntp;
            red4((float4*)(sp + off1), e10, e11, e12, e13);
            red4((float4*)(ap + off1), a10, a11, a12, a13);
        }
    }
}

// ---------------- kernel 3: normalize + lin_out + relu (mma) ----------------
__global__ __launch_bounds__(256) void node_out_kernel(
    const float* __restrict__ Wout, const float* __restrict__ bout,
    float* __restrict__ out)
{
    extern __shared__ __align__(16) char smem[];
    uint4*  sBF  = (uint4*)smem;                  // Wout hi + lo = 16KB
    float2* sB   = (float2*)(smem + 16384);
    const int tid = threadIdx.x;
    build_bf4(sBF, sBF + 512, Wout, tid, 256);
    if (tid < 32) sB[tid] = make_float2(bout[2 * tid], bout[2 * tid + 1]);
    __syncthreads();

    const int lane = tid & 31;
    const int g = lane >> 2, t = lane & 3;
    const float* accp = (const float*)g_acc4;
    const float* ssp  = (const float*)g_s4;

    const int nTiles = Nn / 16;  // 3125
    const int wStride = gridDim.x * 8;
    for (int tile = blockIdx.x * 8 + (tid >> 5); tile < nTiles; tile += wStride) {
        const int n0 = tile * 16;

        float rg0[16], rg1[16];
#pragma unroll
        for (int q = 0; q < 4; q++) {
            float4 a0 = *(const float4*)(accp + (n0 + g) * 64 + 16 * t + 4 * q);
            float4 s0 = *(const float4*)(ssp  + (n0 + g) * 64 + 16 * t + 4 * q);
            rg0[4 * q + 0] = a0.x / (s0.x + 1e-16f);
            rg0[4 * q + 1] = a0.y / (s0.y + 1e-16f);
            rg0[4 * q + 2] = a0.z / (s0.z + 1e-16f);
            rg0[4 * q + 3] = a0.w / (s0.w + 1e-16f);
            float4 a1 = *(const float4*)(accp + (n0 + g + 8) * 64 + 16 * t + 4 * q);
            float4 s1 = *(const float4*)(ssp  + (n0 + g + 8) * 64 + 16 * t + 4 * q);
            rg1[4 * q + 0] = a1.x / (s1.x + 1e-16f);
            rg1[4 * q + 1] = a1.y / (s1.y + 1e-16f);
            rg1[4 * q + 2] = a1.z / (s1.z + 1e-16f);
            rg1[4 * q + 3] = a1.w / (s1.w + 1e-16f);
        }

        uint32_t Ah[16], Al[16];
#pragma unroll
        for (int nt = 0; nt < 8; nt++) {
            int kt = nt >> 1, half = nt & 1, slot = kt * 4 + 2 * half;
            pack_hl_f16(rg0[2 * nt], rg0[2 * nt + 1], Ah[slot],     Al[slot]);
            pack_hl_f16(rg1[2 * nt], rg1[2 * nt + 1], Ah[slot + 1], Al[slot + 1]);
        }

        float D[32];
#pragma unroll
        for (int i = 0; i < 32; i++) D[i] = 0.f;
        gemm3p(D, Ah, Al, sBF, sBF + 512, lane);

#pragma unroll
        for (int nt = 0; nt < 8; nt++) {
            int c0 = 8 * nt + 2 * t;
            float2 bb = sB[4 * nt + t];
            *(float2*)&out[(n0 + g    ) * 64 + c0] =
                make_float2(fmaxf(D[nt * 4 + 0] + bb.x, 0.f),
                            fmaxf(D[nt * 4 + 1] + bb.y, 0.f));
            *(float2*)&out[(n0 + g + 8) * 64 + c0] =
                make_float2(fmaxf(D[nt * 4 + 2] + bb.x, 0.f),
                            fmaxf(D[nt * 4 + 3] + bb.y, 0.f));
        }
    }
}

// ---------------- launch ----------------
extern "C" void kernel_launch(void* const* d_in, const int* in_sizes, int n_in,
                              void* d_out, int out_size)
{
    const float* x    = (const float*)d_in[0];
    const float* pos  = (const float*)d_in[1];
    const int*   ei   = (const int*)  d_in[2];
    const float* Win  = (const float*)d_in[3];
    const float* bin  = (const float*)d_in[4];
    const float* Wlin = (const float*)d_in[5];
    const float* Wsrc = (const float*)d_in[6];
    const float* Wdst = (const float*)d_in[7];
    const float* Wp1  = (const float*)d_in[8];
    const float* bp1  = (const float*)d_in[9];
    const float* Wp2  = (const float*)d_in[10];
    const float* bp2  = (const float*)d_in[11];
    const float* Wa1  = (const float*)d_in[12];
    const float* ba1  = (const float*)d_in[13];
    const float* Wa2  = (const float*)d_in[14];
    const float* ba2  = (const float*)d_in[15];
    const float* Wout = (const float*)d_in[16];
    const float* bout = (const float*)d_in[17];

    const int projSmem = 65536 + 256;
    const int outSmem  = 16384 + 256;
    cudaFuncSetAttribute(node_proj_kernel,  cudaFuncAttributeMaxDynamicSharedMemorySize, projSmem);
    cudaFuncSetAttribute(edge_fused_kernel, cudaFuncAttributeMaxDynamicSharedMemorySize, ESM_TOTAL);
    cudaFuncSetAttribute(node_out_kernel,   cudaFuncAttributeMaxDynamicSharedMemorySize, outSmem);

    fold_kernel<<<48, 256>>>(Wsrc, Wdst, Wp2, Wa1, bp2, ba1);
    init_kernel<<<(Nn * 16 + 255) / 256, 256>>>();
    node_proj_kernel<<<391, 256, projSmem>>>(x, Win, bin, Wlin);
    edge_fused_kernel<<<296, 256, ESM_TOTAL>>>(pos, ei, Wp1, bp1, Wp2, bp2,
                                               Wa2, ba2);
    node_out_kernel<<<391, 256, outSmem>>>(Wout, bout, (float*)d_out);
}

// round 13
// speedup vs baseline: 1.0208x; 1.0208x over previous
#include <cuda_runtime.h>
#include <cuda_fp16.h>
#include <cstdint>
#include <cstddef>

#define Nn 50000
#define Ee 800000

// ---------------- scratch (static device globals; no allocation) ----------------
__device__ float4 g_s4  [Nn * 16];
__device__ float4 g_acc4[Nn * 16];
__device__ __align__(16) __half g_vh[Nn * 64];
__device__ __align__(16) __half g_Qh[Nn * 64];
__device__ __align__(16) __half g_Ph[Nn * 64];
__device__ float g_WsA[4096];
__device__ float g_WdA[4096];
__device__ float g_WpA[4096];
__device__ float g_cvec[64];
// dst-sort machinery
__device__ int  g_binCnt[Nn];
__device__ int  g_binCur[Nn];
__device__ int2 g_esd[Ee];     // sorted (src,dst) records

// ---------------- helpers ----------------
__device__ __forceinline__ uint32_t pack_f16x2(float a, float b) {
    uint32_t w;
    asm("cvt.rn.f16x2.f32 %0, %1, %2;" : "=r"(w) : "f"(b), "f"(a));  // lo=a, hi=b
    return w;
}
__device__ __forceinline__ void pack_hl_f16(float a, float b, uint32_t& h, uint32_t& l) {
    asm("cvt.rn.f16x2.f32 %0, %1, %2;" : "=r"(h) : "f"(b), "f"(a));
    __half2 h2 = *reinterpret_cast<__half2*>(&h);
    float la = a - __half2float(h2.x);
    float lb = b - __half2float(h2.y);
    asm("cvt.rn.f16x2.f32 %0, %1, %2;" : "=r"(l) : "f"(lb), "f"(la));
}
__device__ __forceinline__ float2 h2f2(uint32_t w) {
    __half2 h = *reinterpret_cast<__half2*>(&w);
    return make_float2(__half2float(h.x), __half2float(h.y));
}
__device__ __forceinline__ void red4(float4* p, float a, float b, float c, float d) {
    asm volatile("red.global.add.v4.f32 [%0], {%1, %2, %3, %4};"
                 :: "l"(p), "f"(a), "f"(b), "f"(c), "f"(d) : "memory");
}
__device__ __forceinline__ void mma_f16(float* d, const uint32_t* a, uint32_t b0, uint32_t b1) {
    asm volatile(
        "mma.sync.aligned.m16n8k16.row.col.f32.f16.f16.f32 "
        "{%0,%1,%2,%3},{%4,%5,%6,%7},{%8,%9},{%0,%1,%2,%3};"
        : "+f"(d[0]), "+f"(d[1]), "+f"(d[2]), "+f"(d[3])
        : "r"(a[0]), "r"(a[1]), "r"(a[2]), "r"(a[3]), "r"(b0), "r"(b1));
}
__device__ __forceinline__ void gemm1p(float* D, const uint32_t* Ah,
                                       const uint4* __restrict__ bf, int lane) {
#pragma unroll
    for (int kt = 0; kt < 4; kt++)
#pragma unroll
        for (int ntp = 0; ntp < 4; ntp++) {
            uint4 b = bf[(kt * 4 + ntp) * 32 + lane];
            mma_f16(D + (2 * ntp)     * 4, Ah + kt * 4, b.x, b.y);
            mma_f16(D + (2 * ntp + 1) * 4, Ah + kt * 4, b.z, b.w);
        }
}
__device__ __forceinline__ void gemm2p(float* D, const uint32_t* Ah,
                                       const uint4* __restrict__ bfH,
                                       const uint4* __restrict__ bfL, int lane) {
#pragma unroll
    for (int kt = 0; kt < 4; kt++)
#pragma unroll
        for (int ntp = 0; ntp < 4; ntp++) {
            uint4 bh = bfH[(kt * 4 + ntp) * 32 + lane];
            mma_f16(D + (2 * ntp)     * 4, Ah + kt * 4, bh.x, bh.y);
            mma_f16(D + (2 * ntp + 1) * 4, Ah + kt * 4, bh.z, bh.w);
            uint4 bl = bfL[(kt * 4 + ntp) * 32 + lane];
            mma_f16(D + (2 * ntp)     * 4, Ah + kt * 4, bl.x, bl.y);
            mma_f16(D + (2 * ntp + 1) * 4, Ah + kt * 4, bl.z, bl.w);
        }
}
__device__ __forceinline__ void gemm3p(float* D, const uint32_t* Ah, const uint32_t* Al,
                                       const uint4* __restrict__ bfH,
                                       const uint4* __restrict__ bfL, int lane) {
#pragma unroll
    for (int kt = 0; kt < 4; kt++)
#pragma unroll
        for (int ntp = 0; ntp < 4; ntp++) {
            uint4 bh = bfH[(kt * 4 + ntp) * 32 + lane];
            mma_f16(D + (2 * ntp)     * 4, Ah + kt * 4, bh.x, bh.y);
            mma_f16(D + (2 * ntp + 1) * 4, Ah + kt * 4, bh.z, bh.w);
            mma_f16(D + (2 * ntp)     * 4, Al + kt * 4, bh.x, bh.y);
            mma_f16(D + (2 * ntp + 1) * 4, Al + kt * 4, bh.z, bh.w);
            uint4 bl = bfL[(kt * 4 + ntp) * 32 + lane];
            mma_f16(D + (2 * ntp)     * 4, Ah + kt * 4, bl.x, bl.y);
            mma_f16(D + (2 * ntp + 1) * 4, Ah + kt * 4, bl.z, bl.w);
        }
}

__device__ __forceinline__ void build_bf4(uint4* dstH, uint4* dstL,
                                          const float* __restrict__ W,
                                          int tid, int nth) {
    for (int i = tid; i < 1024; i += nth) {
        int kt = i >> 8, nt = (i >> 5) & 7, lane = i & 31;
        int g = lane >> 2, t = lane & 3;
        int col = 8 * nt + g;
        int k0  = 16 * kt + 2 * t;
        float w00 = W[(k0    ) * 64 + col];
        float w01 = W[(k0 + 1) * 64 + col];
        float w10 = W[(k0 + 8) * 64 + col];
        float w11 = W[(k0 + 9) * 64 + col];
        uint32_t h0, l0, h1, l1;
        pack_hl_f16(w00, w01, h0, l0);
        pack_hl_f16(w10, w11, h1, l1);
        uint32_t* pH = (uint32_t*)&dstH[(kt * 4 + (nt >> 1)) * 32 + lane];
        int sub = (nt & 1) * 2;
        pH[sub] = h0; pH[sub + 1] = h1;
        if (dstL) {
            uint32_t* pL = (uint32_t*)&dstL[(kt * 4 + (nt >> 1)) * 32 + lane];
            pL[sub] = l0; pL[sub + 1] = l1;
        }
    }
}

// ---------------- kernel -1: fold weight products (fp32) ----------------
__global__ __launch_bounds__(256) void fold_kernel(
    const float* __restrict__ Wsrc, const float* __restrict__ Wdst,
    const float* __restrict__ Wp2,  const float* __restrict__ Wa1,
    const float* __restrict__ bp2,  const float* __restrict__ ba1)
{
    int gid = blockIdx.x * blockDim.x + threadIdx.x;
    if (gid < 3 * 4096) {
        int m = gid >> 12;
        int idx = gid & 4095;
        int i = idx >> 6, j = idx & 63;
        const float* A = (m == 0) ? Wsrc : (m == 1) ? Wdst : Wp2;
        float s = 0.f;
        for (int k = 0; k < 64; k++) s = fmaf(A[i * 64 + k], Wa1[k * 64 + j], s);
        float* O = (m == 0) ? g_WsA : (m == 1) ? g_WdA : g_WpA;
        O[idx] = s;
    }
    if (gid < 64) {
        float s = ba1[gid];
        for (int k = 0; k < 64; k++) s = fmaf(bp2[k], Wa1[k * 64 + gid], s);
        g_cvec[gid] = s;
    }
}

// ---------------- kernel 0: init (reduction buffers + histogram) ----------------
__global__ __launch_bounds__(256) void init_kernel() {
    int i = blockIdx.x * blockDim.x + threadIdx.x;
    if (i < Nn * 16) {
        g_s4[i]   = make_float4(0.f, 0.f, 0.f, 0.f);
        g_acc4[i] = make_float4(0.f, 0.f, 0.f, 0.f);
    }
    if (i < Nn) g_binCnt[i] = 0;
}

// ---------------- sort kernels ----------------
__global__ __launch_bounds__(256) void hist_kernel(const int* __restrict__ ei) {
    int e = blockIdx.x * blockDim.x + threadIdx.x;
    if (e < Ee) atomicAdd(&g_binCnt[ei[Ee + e]], 1);
}

__global__ __launch_bounds__(1024) void scan_kernel() {
    __shared__ int wsum[32];
    __shared__ int s_carry;
    int tid = threadIdx.x, lane = tid & 31, wid = tid >> 5;
    if (tid == 0) s_carry = 0;
    __syncthreads();
    for (int base = 0; base < Nn; base += 1024) {
        int i = base + tid;
        int v = (i < Nn) ? g_binCnt[i] : 0;
        int incl = v;
#pragma unroll
        for (int o = 1; o < 32; o <<= 1) {
            int u = __shfl_up_sync(0xffffffffu, incl, o);
            if (lane >= o) incl += u;
        }
        if (lane == 31) wsum[wid] = incl;
        __syncthreads();
        if (wid == 0) {
            int w = wsum[lane];
            int wi = w;
#pragma unroll
            for (int o = 1; o < 32; o <<= 1) {
                int u = __shfl_up_sync(0xffffffffu, wi, o);
                if (lane >= o) wi += u;
            }
            wsum[lane] = wi - w;  // exclusive warp offset
        }
        __syncthreads();
        int excl = incl - v + wsum[wid] + s_carry;
        if (i < Nn) g_binCur[i] = excl;
        __syncthreads();
        if (tid == 1023) s_carry = excl + v;
        __syncthreads();
    }
}

__global__ __launch_bounds__(256) void scatter_kernel(const int* __restrict__ ei) {
    int e = blockIdx.x * blockDim.x + threadIdx.x;
    if (e < Ee) {
        int s = ei[e], d = ei[Ee + e];
        int p = atomicAdd(&g_binCur[d], 1);
        g_esd[p] = make_int2(s, d);
    }
}

// ---------------- kernel 1: node projections ----------------
__global__ __launch_bounds__(256) void node_proj_kernel(
    const float* __restrict__ x,
    const float* __restrict__ Win,  const float* __restrict__ bin,
    const float* __restrict__ Wlin)
{
    extern __shared__ __align__(16) char smem[];
    uint4*  sBF  = (uint4*)smem;                       // 8 x 512 uint4 = 64KB
    float2* sBin = (float2*)(smem + 65536);
    const int tid = threadIdx.x;

    build_bf4(sBF + 0 * 512, sBF + 1 * 512, Win,  tid, 256);
    build_bf4(sBF + 2 * 512, sBF + 3 * 512, Wlin, tid, 256);
    build_bf4(sBF + 4 * 512, sBF + 5 * 512, (const float*)g_WsA, tid, 256);
    build_bf4(sBF + 6 * 512, sBF + 7 * 512, (const float*)g_WdA, tid, 256);
    if (tid < 32) sBin[tid] = make_float2(bin[2 * tid], bin[2 * tid + 1]);
    __syncthreads();

    const int lane = tid & 31;
    const int g = lane >> 2, t = lane & 3;

    __half* outs[3] = { g_vh, g_Qh, g_Ph };

    const int nTiles = Nn / 16;  // 3125
    const int wStride = gridDim.x * 8;
    for (int tile = blockIdx.x * 8 + (tid >> 5); tile < nTiles; tile += wStride) {
        const int n0 = tile * 16;

        uint32_t Ah[16];
#pragma unroll
        for (int kt = 0; kt < 4; kt++)
#pragma unroll
            for (int half = 0; half < 2; half++)
#pragma unroll
                for (int h = 0; h < 2; h++) {
                    float2 xx = *(const float2*)&x[(n0 + g + 8 * h) * 64 + 16 * kt + 2 * t + 8 * half];
                    Ah[kt * 4 + h + 2 * half] = pack_f16x2(xx.x, xx.y);
                }

        float D[32];
#pragma unroll
        for (int i = 0; i < 32; i++) D[i] = 0.f;
        gemm2p(D, Ah, sBF + 0 * 512, sBF + 1 * 512, lane);

        uint32_t Ah2[16];
#pragma unroll
        for (int nt = 0; nt < 8; nt++) {
            float2 bb = sBin[4 * nt + t];
            int kt = nt >> 1, half = nt & 1, slot = kt * 4 + 2 * half;
            Ah2[slot]     = pack_f16x2(fmaxf(D[nt * 4 + 0] + bb.x, 0.f),
                                       fmaxf(D[nt * 4 + 1] + bb.y, 0.f));
            Ah2[slot + 1] = pack_f16x2(fmaxf(D[nt * 4 + 2] + bb.x, 0.f),
                                       fmaxf(D[nt * 4 + 3] + bb.y, 0.f));
        }

#pragma unroll
        for (int m = 0; m < 3; m++) {
#pragma unroll
            for (int i = 0; i < 32; i++) D[i] = 0.f;
            gemm2p(D, Ah2, sBF + (2 + 2 * m) * 512, sBF + (3 + 2 * m) * 512, lane);
            __half* o = outs[m];
#pragma unroll
            for (int ntp = 0; ntp < 4; ntp++) {
                int na = 2 * ntp, nb = na + 1;
                uint2 r0 = make_uint2(pack_f16x2(D[na * 4 + 0], D[na * 4 + 1]),
                                      pack_f16x2(D[nb * 4 + 0], D[nb * 4 + 1]));
                uint2 r8 = make_uint2(pack_f16x2(D[na * 4 + 2], D[na * 4 + 3]),
                                      pack_f16x2(D[nb * 4 + 2], D[nb * 4 + 3]));
                *(uint2*)(o + (n0 + g    ) * 64 + 16 * t + 4 * ntp) = r0;
                *(uint2*)(o + (n0 + g + 8) * 64 + 16 * t + 4 * ntp) = r8;
            }
        }
    }
}

// ---------------- kernel 2: fused edge kernel (dst-sorted, merged scatter) ----------------
#define ESM_WP1   24576
#define ESM_BP2   25600
#define ESM_CV    25856
#define ESM_BA2   26112
#define ESM_TOTAL 26624

__global__ __launch_bounds__(256, 2) void edge_fused_kernel(
    const float* __restrict__ pos,
    const float* __restrict__ Wp1, const float* __restrict__ bp1,
    const float* __restrict__ Wp2, const float* __restrict__ bp2,
    const float* __restrict__ Wa2, const float* __restrict__ ba2)
{
    extern __shared__ __align__(16) char smem[];
    uint4*  sBF  = (uint4*)smem;
    float4* sWp1 = (float4*)(smem + ESM_WP1);
    float2* sBp2 = (float2*)(smem + ESM_BP2);
    float2* sCv  = (float2*)(smem + ESM_CV);
    float2* sBa2 = (float2*)(smem + ESM_BA2);

    const int tid = threadIdx.x;
    build_bf4(sBF + 0 * 512, (uint4*)0, Wp2,                 tid, 256);
    build_bf4(sBF + 1 * 512, (uint4*)0, (const float*)g_WpA, tid, 256);
    build_bf4(sBF + 2 * 512, (uint4*)0, Wa2,                 tid, 256);
    if (tid < 64)
        sWp1[tid] = make_float4(Wp1[tid], Wp1[64 + tid], Wp1[128 + tid], bp1[tid]);
    if (tid < 32) {
        sBp2[tid] = make_float2(bp2[2 * tid], bp2[2 * tid + 1]);
        sCv[tid]  = make_float2(g_cvec[2 * tid], g_cvec[2 * tid + 1]);
        sBa2[tid] = make_float2(ba2[2 * tid], ba2[2 * tid + 1]);
    }
    __syncthreads();

    const int lane = tid & 31;
    const int g = lane >> 2, t = lane & 3;

    const uint4* bfP2h = sBF + 0 * 512;
    const uint4* bfPAh = sBF + 1 * 512;
    const uint4* bfA2h = sBF + 2 * 512;

    const int nTiles = Ee / 16;          // 50000
    const int wStride = gridDim.x * 8;

    int tile = blockIdx.x * 8 + (tid >> 5);

    int pS = 0, pD = 0;
    float pr0 = 0.f, pr1 = 0.f, pr2 = 0.f;
    if (tile < nTiles && lane < 16) {
        int2 sd = __ldg(&g_esd[tile * 16 + lane]);
        pS = sd.x; pD = sd.y;
        pr0 = __ldg(&pos[pD * 3 + 0]) - __ldg(&pos[pS * 3 + 0]);
        pr1 = __ldg(&pos[pD * 3 + 1]) - __ldg(&pos[pS * 3 + 1]);
        pr2 = __ldg(&pos[pD * 3 + 2]) - __ldg(&pos[pS * 3 + 2]);
    }

    for (; tile < nTiles; tile += wStride) {
        // thread owns CONSECUTIVE sorted edges 2g (row g) and 2g+1 (row g+8)
        int sn[2], dn[2];
        float rl[2][3];
#pragma unroll
        for (int h = 0; h < 2; h++) {
            int src = 2 * g + h;
            sn[h]   = __shfl_sync(0xffffffffu, pS, src);
            dn[h]   = __shfl_sync(0xffffffffu, pD, src);
            rl[h][0] = __shfl_sync(0xffffffffu, pr0, src);
            rl[h][1] = __shfl_sync(0xffffffffu, pr1, src);
            rl[h][2] = __shfl_sync(0xffffffffu, pr2, src);
        }

        const int tn = tile + wStride;
        int nS = 0, nD = 0;
        if (tn < nTiles && lane < 16) {
            int2 sd = __ldg(&g_esd[tn * 16 + lane]);
            nS = sd.x; nD = sd.y;
        }

        // hoist P/Q gathers (consumed after G2')
        uint4 P0a = __ldg((const uint4*)(g_Ph + dn[0] * 64 + 16 * t));
        uint4 P0b = __ldg((const uint4*)(g_Ph + dn[0] * 64 + 16 * t + 8));
        uint4 Q0a = __ldg((const uint4*)(g_Qh + sn[0] * 64 + 16 * t));
        uint4 Q0b = __ldg((const uint4*)(g_Qh + sn[0] * 64 + 16 * t + 8));
        uint4 P1a = __ldg((const uint4*)(g_Ph + dn[1] * 64 + 16 * t));
        uint4 P1b = __ldg((const uint4*)(g_Ph + dn[1] * 64 + 16 * t + 8));
        uint4 Q1a = __ldg((const uint4*)(g_Qh + sn[1] * 64 + 16 * t));
        uint4 Q1b = __ldg((const uint4*)(g_Qh + sn[1] * 64 + 16 * t + 8));

        // stage 1: u = relu(rel @ Wp1 + bp1) -> A frags
        uint32_t Au[16];
#pragma unroll
        for (int kt = 0; kt < 4; kt++)
#pragma unroll
            for (int half = 0; half < 2; half++) {
                int c0 = 16 * kt + 2 * t + 8 * half;
                float4 w0 = sWp1[c0];
                float4 w1 = sWp1[c0 + 1];
#pragma unroll
                for (int h = 0; h < 2; h++) {
                    float u0 = fmaxf(fmaf(rl[h][2], w0.z, fmaf(rl[h][1], w0.y,
                               fmaf(rl[h][0], w0.x, w0.w))), 0.f);
                    float u1 = fmaxf(fmaf(rl[h][2], w1.z, fmaf(rl[h][1], w1.y,
                               fmaf(rl[h][0], w1.x, w1.w))), 0.f);
                    Au[kt * 4 + h + 2 * half] = pack_f16x2(u0, u1);
                }
            }

        // G2': h2_pre = u @ WpA
        float Dx[32];
#pragma unroll
        for (int i = 0; i < 32; i++) Dx[i] = 0.f;
        gemm1p(Dx, Au, bfPAh, lane);

        if (tn < nTiles && lane < 16) {
            pr0 = __ldg(&pos[nD * 3 + 0]) - __ldg(&pos[nS * 3 + 0]);
            pr1 = __ldg(&pos[nD * 3 + 1]) - __ldg(&pos[nS * 3 + 1]);
            pr2 = __ldg(&pos[nD * 3 + 2]) - __ldg(&pos[nS * 3 + 2]);
        }
        pS = nS; pD = nD;

        // epi-a: Dx += cvec + P[dn] - Q[sn]
        {
            uint32_t wP0[8] = {P0a.x, P0a.y, P0a.z, P0a.w, P0b.x, P0b.y, P0b.z, P0b.w};
            uint32_t wQ0[8] = {Q0a.x, Q0a.y, Q0a.z, Q0a.w, Q0b.x, Q0b.y, Q0b.z, Q0b.w};
            uint32_t wP1[8] = {P1a.x, P1a.y, P1a.z, P1a.w, P1b.x, P1b.y, P1b.z, P1b.w};
            uint32_t wQ1[8] = {Q1a.x, Q1a.y, Q1a.z, Q1a.w, Q1b.x, Q1b.y, Q1b.z, Q1b.w};
#pragma unroll
            for (int nt = 0; nt < 8; nt++) {
                float2 cv = sCv[4 * nt + t];
                float2 p0 = h2f2(wP0[nt]), q0 = h2f2(wQ0[nt]);
                float2 p1 = h2f2(wP1[nt]), q1 = h2f2(wQ1[nt]);
                Dx[nt * 4 + 0] += cv.x + p0.x - q0.x;
                Dx[nt * 4 + 1] += cv.y + p0.y - q0.y;
                Dx[nt * 4 + 2] += cv.x + p1.x - q1.x;
                Dx[nt * 4 + 3] += cv.y + p1.y - q1.y;
            }
        }

        // G1: delta_raw = u @ Wp2 (latency filler)
        float D1[32];
#pragma unroll
        for (int i = 0; i < 32; i++) D1[i] = 0.f;
        gemm1p(D1, Au, bfP2h, lane);

        uint32_t dltp[16];
#pragma unroll
        for (int nt = 0; nt < 8; nt++) {
            float2 bb = sBp2[4 * nt + t];
            dltp[2 * nt]     = pack_f16x2(D1[nt * 4 + 0] + bb.x, D1[nt * 4 + 1] + bb.y);
            dltp[2 * nt + 1] = pack_f16x2(D1[nt * 4 + 2] + bb.x, D1[nt * 4 + 3] + bb.y);
        }

        // epi-b: h2 = relu(Dx) -> A frags
#pragma unroll
        for (int nt = 0; nt < 8; nt++) {
            int kt = nt >> 1, half = nt & 1, slot = kt * 4 + 2 * half;
            Au[slot]     = pack_f16x2(fmaxf(Dx[nt * 4 + 0], 0.f), fmaxf(Dx[nt * 4 + 1], 0.f));
            Au[slot + 1] = pack_f16x2(fmaxf(Dx[nt * 4 + 2], 0.f), fmaxf(Dx[nt * 4 + 3], 0.f));
        }

        // v gathers (covered by G3)
        uint4 v0a = __ldg((const uint4*)(g_vh + sn[0] * 64 + 16 * t));
        uint4 v0b = __ldg((const uint4*)(g_vh + sn[0] * 64 + 16 * t + 8));
        uint4 v1a = __ldg((const uint4*)(g_vh + sn[1] * 64 + 16 * t));
        uint4 v1b = __ldg((const uint4*)(g_vh + sn[1] * 64 + 16 * t + 8));

        // G3: logits = h2 @ Wa2
#pragma unroll
        for (int i = 0; i < 32; i++) Dx[i] = 0.f;
        gemm1p(Dx, Au, bfA2h, lane);

        // final epi with hierarchical dst-merge
        uint32_t wv0[8] = {v0a.x, v0a.y, v0a.z, v0a.w, v0b.x, v0b.y, v0b.z, v0b.w};
        uint32_t wv1[8] = {v1a.x, v1a.y, v1a.z, v1a.w, v1b.x, v1b.y, v1b.z, v1b.w};
        float* sp_ = (float*)g_s4;
        float* ap_ = (float*)g_acc4;
        float ms[16], ma[16];
        const bool m01 = (dn[0] == dn[1]);
#pragma unroll
        for (int ntp = 0; ntp < 4; ntp++) {
            int na = 2 * ntp, nb = na + 1;
            float2 ba_a = sBa2[4 * na + t], ba_b = sBa2[4 * nb + t];
            float2 va0 = h2f2(wv0[na]), vb0 = h2f2(wv0[nb]);
            float2 va1 = h2f2(wv1[na]), vb1 = h2f2(wv1[nb]);
            float2 dna0 = h2f2(dltp[2 * na]),     dnb0 = h2f2(dltp[2 * nb]);
            float2 dna1 = h2f2(dltp[2 * na + 1]), dnb1 = h2f2(dltp[2 * nb + 1]);
            float e00 = __expf(Dx[na * 4 + 0] + ba_a.x);
            float e01 = __expf(Dx[na * 4 + 1] + ba_a.y);
            float e02 = __expf(Dx[nb * 4 + 0] + ba_b.x);
            float e03 = __expf(Dx[nb * 4 + 1] + ba_b.y);
            float a00 = e00 * (va0.x + dna0.x);
            float a01 = e01 * (va0.y + dna0.y);
            float a02 = e02 * (vb0.x + dnb0.x);
            float a03 = e03 * (vb0.y + dnb0.y);
            float e10 = __expf(Dx[na * 4 + 2] + ba_a.x);
            float e11 = __expf(Dx[na * 4 + 3] + ba_a.y);
            float e12 = __expf(Dx[nb * 4 + 2] + ba_b.x);
            float e13 = __expf(Dx[nb * 4 + 3] + ba_b.y);
            float a10 = e10 * (va1.x + dna1.x);
            float a11 = e11 * (va1.y + dna1.y);
            float a12 = e12 * (vb1.x + dnb1.x);
            float a13 = e13 * (vb1.y + dnb1.y);
            if (m01) {
                ms[4*ntp+0] = e00 + e10; ms[4*ntp+1] = e01 + e11;
                ms[4*ntp+2] = e02 + e12; ms[4*ntp+3] = e03 + e13;
                ma[4*ntp+0] = a00 + a10; ma[4*ntp+1] = a01 + a11;
                ma[4*ntp+2] = a02 + a12; ma[4*ntp+3] = a03 + a13;
            } else {
                ms[4*ntp+0] = e00; ms[4*ntp+1] = e01;
                ms[4*ntp+2] = e02; ms[4*ntp+3] = e03;
                ma[4*ntp+0] = a00; ma[4*ntp+1] = a01;
                ma[4*ntp+2] = a02; ma[4*ntp+3] = a03;
                int off1 = dn[1] * 64 + 16 * t + 4 * ntp;
                red4((float4*)(sp_ + off1), e10, e11, e12, e13);
                red4((float4*)(ap_ + off1), a10, a11, a12, a13);
            }
        }
        // xor-4 neighbor-quad merge (adjacent edge pairs)
        unsigned bal = __ballot_sync(0xffffffffu, m01);
        bool pm01 = (bal >> (lane ^ 4)) & 1u;
        int pdn0 = __shfl_xor_sync(0xffffffffu, dn[0], 4);
        bool joint  = m01 && pm01 && (dn[0] == pdn0);
        bool absorb = joint && ((g & 1) == 0);
        bool dead   = joint && ((g & 1) == 1);
#pragma unroll
        for (int i = 0; i < 16; i++) {
            float pv = __shfl_xor_sync(0xffffffffu, ms[i], 4);
            if (absorb) ms[i] += pv;
        }
#pragma unroll
        for (int i = 0; i < 16; i++) {
            float pv = __shfl_xor_sync(0xffffffffu, ma[i], 4);
            if (absorb) ma[i] += pv;
        }
        if (!dead) {
            int off0 = dn[0] * 64 + 16 * t;
#pragma unroll
            for (int q = 0; q < 4; q++) {
                red4((float4*)(sp_ + off0 + 4 * q), ms[4*q], ms[4*q+1], ms[4*q+2], ms[4*q+3]);
                red4((float4*)(ap_ + off0 + 4 * q), ma[4*q], ma[4*q+1], ma[4*q+2], ma[4*q+3]);
            }
        }
    }
}

// ---------------- kernel 3: normalize + lin_out + relu (mma) ----------------
__global__ __launch_bounds__(256) void node_out_kernel(
    const float* __restrict__ Wout, const float* __restrict__ bout,
    float* __restrict__ out)
{
    extern __shared__ __align__(16) char smem[];
    uint4*  sBF  = (uint4*)smem;                  // Wout hi + lo = 16KB
    float2* sB   = (float2*)(smem + 16384);
    const int tid = threadIdx.x;
    build_bf4(sBF, sBF + 512, Wout, tid, 256);
    if (tid < 32) sB[tid] = make_float2(bout[2 * tid], bout[2 * tid + 1]);
    __syncthreads();

    const int lane = tid & 31;
    const int g = lane >> 2, t = lane & 3;
    const float* accp = (const float*)g_acc4;
    const float* ssp  = (const float*)g_s4;

    const int nTiles = Nn / 16;  // 3125
    const int wStride = gridDim.x * 8;
    for (int tile = blockIdx.x * 8 + (tid >> 5); tile < nTiles; tile += wStride) {
        const int n0 = tile * 16;

        float rg0[16], rg1[16];
#pragma unroll
        for (int q = 0; q < 4; q++) {
            float4 a0 = *(const float4*)(accp + (n0 + g) * 64 + 16 * t + 4 * q);
            float4 s0 = *(const float4*)(ssp  + (n0 + g) * 64 + 16 * t + 4 * q);
            rg0[4 * q + 0] = a0.x / (s0.x + 1e-16f);
            rg0[4 * q + 1] = a0.y / (s0.y + 1e-16f);
            rg0[4 * q + 2] = a0.z / (s0.z + 1e-16f);
            rg0[4 * q + 3] = a0.w / (s0.w + 1e-16f);
            float4 a1 = *(const float4*)(accp + (n0 + g + 8) * 64 + 16 * t + 4 * q);
            float4 s1 = *(const float4*)(ssp  + (n0 + g + 8) * 64 + 16 * t + 4 * q);
            rg1[4 * q + 0] = a1.x / (s1.x + 1e-16f);
            rg1[4 * q + 1] = a1.y / (s1.y + 1e-16f);
            rg1[4 * q + 2] = a1.z / (s1.z + 1e-16f);
            rg1[4 * q + 3] = a1.w / (s1.w + 1e-16f);
        }

        uint32_t Ah[16], Al[16];
#pragma unroll
        for (int nt = 0; nt < 8; nt++) {
            int kt = nt >> 1, half = nt & 1, slot = kt * 4 + 2 * half;
            pack_hl_f16(rg0[2 * nt], rg0[2 * nt + 1], Ah[slot],     Al[slot]);
            pack_hl_f16(rg1[2 * nt], rg1[2 * nt + 1], Ah[slot + 1], Al[slot + 1]);
        }

        float D[32];
#pragma unroll
        for (int i = 0; i < 32; i++) D[i] = 0.f;
        gemm3p(D, Ah, Al, sBF, sBF + 512, lane);

#pragma unroll
        for (int nt = 0; nt < 8; nt++) {
            int c0 = 8 * nt + 2 * t;
            float2 bb = sB[4 * nt + t];
            *(float2*)&out[(n0 + g    ) * 64 + c0] =
                make_float2(fmaxf(D[nt * 4 + 0] + bb.x, 0.f),
                            fmaxf(D[nt * 4 + 1] + bb.y, 0.f));
            *(float2*)&out[(n0 + g + 8) * 64 + c0] =
                make_float2(fmaxf(D[nt * 4 + 2] + bb.x, 0.f),
                            fmaxf(D[nt * 4 + 3] + bb.y, 0.f));
        }
    }
}

// ---------------- launch ----------------
extern "C" void kernel_launch(void* const* d_in, const int* in_sizes, int n_in,
                              void* d_out, int out_size)
{
    const float* x    = (const float*)d_in[0];
    const float* pos  = (const float*)d_in[1];
    const int*   ei   = (const int*)  d_in[2];
    const float* Win  = (const float*)d_in[3];
    const float* bin  = (const float*)d_in[4];
    const float* Wlin = (const float*)d_in[5];
    const float* Wsrc = (const float*)d_in[6];
    const float* Wdst = (const float*)d_in[7];
    const float* Wp1  = (const float*)d_in[8];
    const float* bp1  = (const float*)d_in[9];
    const float* Wp2  = (const float*)d_in[10];
    const float* bp2  = (const float*)d_in[11];
    const float* Wa1  = (const float*)d_in[12];
    const float* ba1  = (const float*)d_in[13];
    const float* Wa2  = (const float*)d_in[14];
    const float* ba2  = (const float*)d_in[15];
    const float* Wout = (const float*)d_in[16];
    const float* bout = (const float*)d_in[17];

    const int projSmem = 65536 + 256;
    const int outSmem  = 16384 + 256;
    cudaFuncSetAttribute(node_proj_kernel,  cudaFuncAttributeMaxDynamicSharedMemorySize, projSmem);
    cudaFuncSetAttribute(edge_fused_kernel, cudaFuncAttributeMaxDynamicSharedMemorySize, ESM_TOTAL);
    cudaFuncSetAttribute(node_out_kernel,   cudaFuncAttributeMaxDynamicSharedMemorySize, outSmem);

    init_kernel<<<(Nn * 16 + 255) / 256, 256>>>();
    hist_kernel<<<(Ee + 255) / 256, 256>>>(ei);
    scan_kernel<<<1, 1024>>>();
    scatter_kernel<<<(Ee + 255) / 256, 256>>>(ei);
    fold_kernel<<<48, 256>>>(Wsrc, Wdst, Wp2, Wa1, bp2, ba1);
    node_proj_kernel<<<391, 256, projSmem>>>(x, Win, bin, Wlin);
    edge_fused_kernel<<<296, 256, ESM_TOTAL>>>(pos, Wp1, bp1, Wp2, bp2, Wa2, ba2);
    node_out_kernel<<<391, 256, outSmem>>>(Wout, bout, (float*)d_out);
}

// round 14
// speedup vs baseline: 1.1715x; 1.1477x over previous
#include <cuda_runtime.h>
#include <cuda_fp16.h>
#include <cstdint>
#include <cstddef>

#define Nn 50000
#define Ee 800000

// ---------------- scratch (static device globals; no allocation) ----------------
__device__ float4 g_s4  [Nn * 16];
__device__ float4 g_acc4[Nn * 16];
__device__ __align__(16) __half g_vh[Nn * 64];
__device__ __align__(16) __half g_Qh[Nn * 64];
__device__ __align__(16) __half g_Ph[Nn * 64];
__device__ float g_WsA[4096];
__device__ float g_WdA[4096];
__device__ float g_WpA[4096];
__device__ float g_cvec[64];
// dst-sort machinery
__device__ int  g_binCnt[Nn];
__device__ int  g_binCur[Nn];
__device__ int  g_blkSum[64];
__device__ int  g_blkOff[64];
__device__ int2 g_esd[Ee];     // sorted (src,dst) records

// ---------------- helpers ----------------
__device__ __forceinline__ uint32_t pack_f16x2(float a, float b) {
    uint32_t w;
    asm("cvt.rn.f16x2.f32 %0, %1, %2;" : "=r"(w) : "f"(b), "f"(a));  // lo=a, hi=b
    return w;
}
__device__ __forceinline__ void pack_hl_f16(float a, float b, uint32_t& h, uint32_t& l) {
    asm("cvt.rn.f16x2.f32 %0, %1, %2;" : "=r"(h) : "f"(b), "f"(a));
    __half2 h2 = *reinterpret_cast<__half2*>(&h);
    float la = a - __half2float(h2.x);
    float lb = b - __half2float(h2.y);
    asm("cvt.rn.f16x2.f32 %0, %1, %2;" : "=r"(l) : "f"(lb), "f"(la));
}
__device__ __forceinline__ float2 h2f2(uint32_t w) {
    __half2 h = *reinterpret_cast<__half2*>(&w);
    return make_float2(__half2float(h.x), __half2float(h.y));
}
__device__ __forceinline__ void red4(float4* p, float a, float b, float c, float d) {
    asm volatile("red.global.add.v4.f32 [%0], {%1, %2, %3, %4};"
                 :: "l"(p), "f"(a), "f"(b), "f"(c), "f"(d) : "memory");
}
__device__ __forceinline__ void mma_f16(float* d, const uint32_t* a, uint32_t b0, uint32_t b1) {
    asm volatile(
        "mma.sync.aligned.m16n8k16.row.col.f32.f16.f16.f32 "
        "{%0,%1,%2,%3},{%4,%5,%6,%7},{%8,%9},{%0,%1,%2,%3};"
        : "+f"(d[0]), "+f"(d[1]), "+f"(d[2]), "+f"(d[3])
        : "r"(a[0]), "r"(a[1]), "r"(a[2]), "r"(a[3]), "r"(b0), "r"(b1));
}
__device__ __forceinline__ void gemm1p(float* D, const uint32_t* Ah,
                                       const uint4* __restrict__ bf, int lane) {
#pragma unroll
    for (int kt = 0; kt < 4; kt++)
#pragma unroll
        for (int ntp = 0; ntp < 4; ntp++) {
            uint4 b = bf[(kt * 4 + ntp) * 32 + lane];
            mma_f16(D + (2 * ntp)     * 4, Ah + kt * 4, b.x, b.y);
            mma_f16(D + (2 * ntp + 1) * 4, Ah + kt * 4, b.z, b.w);
        }
}
__device__ __forceinline__ void gemm2p(float* D, const uint32_t* Ah,
                                       const uint4* __restrict__ bfH,
                                       const uint4* __restrict__ bfL, int lane) {
#pragma unroll
    for (int kt = 0; kt < 4; kt++)
#pragma unroll
        for (int ntp = 0; ntp < 4; ntp++) {
            uint4 bh = bfH[(kt * 4 + ntp) * 32 + lane];
            mma_f16(D + (2 * ntp)     * 4, Ah + kt * 4, bh.x, bh.y);
            mma_f16(D + (2 * ntp + 1) * 4, Ah + kt * 4, bh.z, bh.w);
            uint4 bl = bfL[(kt * 4 + ntp) * 32 + lane];
            mma_f16(D + (2 * ntp)     * 4, Ah + kt * 4, bl.x, bl.y);
            mma_f16(D + (2 * ntp + 1) * 4, Ah + kt * 4, bl.z, bl.w);
        }
}
__device__ __forceinline__ void gemm3p(float* D, const uint32_t* Ah, const uint32_t* Al,
                                       const uint4* __restrict__ bfH,
                                       const uint4* __restrict__ bfL, int lane) {
#pragma unroll
    for (int kt = 0; kt < 4; kt++)
#pragma unroll
        for (int ntp = 0; ntp < 4; ntp++) {
            uint4 bh = bfH[(kt * 4 + ntp) * 32 + lane];
            mma_f16(D + (2 * ntp)     * 4, Ah + kt * 4, bh.x, bh.y);
            mma_f16(D + (2 * ntp + 1) * 4, Ah + kt * 4, bh.z, bh.w);
            mma_f16(D + (2 * ntp)     * 4, Al + kt * 4, bh.x, bh.y);
            mma_f16(D + (2 * ntp + 1) * 4, Al + kt * 4, bh.z, bh.w);
            uint4 bl = bfL[(kt * 4 + ntp) * 32 + lane];
            mma_f16(D + (2 * ntp)     * 4, Ah + kt * 4, bl.x, bl.y);
            mma_f16(D + (2 * ntp + 1) * 4, Ah + kt * 4, bl.z, bl.w);
        }
}

__device__ __forceinline__ void build_bf4(uint4* dstH, uint4* dstL,
                                          const float* __restrict__ W,
                                          int tid, int nth) {
    for (int i = tid; i < 1024; i += nth) {
        int kt = i >> 8, nt = (i >> 5) & 7, lane = i & 31;
        int g = lane >> 2, t = lane & 3;
        int col = 8 * nt + g;
        int k0  = 16 * kt + 2 * t;
        float w00 = W[(k0    ) * 64 + col];
        float w01 = W[(k0 + 1) * 64 + col];
        float w10 = W[(k0 + 8) * 64 + col];
        float w11 = W[(k0 + 9) * 64 + col];
        uint32_t h0, l0, h1, l1;
        pack_hl_f16(w00, w01, h0, l0);
        pack_hl_f16(w10, w11, h1, l1);
        uint32_t* pH = (uint32_t*)&dstH[(kt * 4 + (nt >> 1)) * 32 + lane];
        int sub = (nt & 1) * 2;
        pH[sub] = h0; pH[sub + 1] = h1;
        if (dstL) {
            uint32_t* pL = (uint32_t*)&dstL[(kt * 4 + (nt >> 1)) * 32 + lane];
            pL[sub] = l0; pL[sub + 1] = l1;
        }
    }
}

// ---------------- kernel -1: fold weight products (fp32) ----------------
__global__ __launch_bounds__(256) void fold_kernel(
    const float* __restrict__ Wsrc, const float* __restrict__ Wdst,
    const float* __restrict__ Wp2,  const float* __restrict__ Wa1,
    const float* __restrict__ bp2,  const float* __restrict__ ba1)
{
    int gid = blockIdx.x * blockDim.x + threadIdx.x;
    if (gid < 3 * 4096) {
        int m = gid >> 12;
        int idx = gid & 4095;
        int i = idx >> 6, j = idx & 63;
        const float* A = (m == 0) ? Wsrc : (m == 1) ? Wdst : Wp2;
        float s = 0.f;
        for (int k = 0; k < 64; k++) s = fmaf(A[i * 64 + k], Wa1[k * 64 + j], s);
        float* O = (m == 0) ? g_WsA : (m == 1) ? g_WdA : g_WpA;
        O[idx] = s;
    }
    if (gid < 64) {
        float s = ba1[gid];
        for (int k = 0; k < 64; k++) s = fmaf(bp2[k], Wa1[k * 64 + gid], s);
        g_cvec[gid] = s;
    }
}

// ---------------- kernel 0: init (reduction buffers + histogram zero) ----------------
__global__ __launch_bounds__(256) void init_kernel() {
    int i = blockIdx.x * blockDim.x + threadIdx.x;
    if (i < Nn * 16) {
        g_s4[i]   = make_float4(0.f, 0.f, 0.f, 0.f);
        g_acc4[i] = make_float4(0.f, 0.f, 0.f, 0.f);
    }
    if (i < Nn) g_binCnt[i] = 0;
}

// ---------------- sort kernels ----------------
__global__ __launch_bounds__(256) void hist_kernel(const int* __restrict__ ei) {
    int e = blockIdx.x * blockDim.x + threadIdx.x;
    if (e < Ee) atomicAdd(&g_binCnt[ei[Ee + e]], 1);
}

// block-local exclusive scan over 1024 bins; block total to g_blkSum
__global__ __launch_bounds__(1024) void scanA_kernel() {
    __shared__ int wsum[32];
    int i = blockIdx.x * 1024 + threadIdx.x;
    int lane = threadIdx.x & 31, wid = threadIdx.x >> 5;
    int v = (i < Nn) ? g_binCnt[i] : 0;
    int incl = v;
#pragma unroll
    for (int o = 1; o < 32; o <<= 1) {
        int u = __shfl_up_sync(0xffffffffu, incl, o);
        if (lane >= o) incl += u;
    }
    if (lane == 31) wsum[wid] = incl;
    __syncthreads();
    if (wid == 0) {
        int w = wsum[lane];
        int wi = w;
#pragma unroll
        for (int o = 1; o < 32; o <<= 1) {
            int u = __shfl_up_sync(0xffffffffu, wi, o);
            if (lane >= o) wi += u;
        }
        wsum[lane] = wi - w;
    }
    __syncthreads();
    int excl = incl - v + wsum[wid];
    if (i < Nn) g_binCur[i] = excl;
    if (threadIdx.x == 1023) g_blkSum[blockIdx.x] = excl + v;
}

// scan 49 block sums (one warp, 2 elements per lane)
__global__ __launch_bounds__(32) void scanB_kernel() {
    const int nBlk = (Nn + 1023) / 1024;  // 49
    int lane = threadIdx.x;
    int a = (lane < nBlk) ? g_blkSum[lane] : 0;
    int b = (lane + 32 < nBlk) ? g_blkSum[lane + 32] : 0;
    int ia = a, ib = b;
#pragma unroll
    for (int o = 1; o < 32; o <<= 1) {
        int u = __shfl_up_sync(0xffffffffu, ia, o);
        if (lane >= o) ia += u;
        int u2 = __shfl_up_sync(0xffffffffu, ib, o);
        if (lane >= o) ib += u2;
    }
    int totA = __shfl_sync(0xffffffffu, ia, 31);
    if (lane < nBlk) g_blkOff[lane] = ia - a;
    if (lane + 32 < nBlk) g_blkOff[lane + 32] = totA + ib - b;
}

// ILP-4 scatter
__global__ __launch_bounds__(256) void scatter_kernel(const int* __restrict__ ei) {
    int base = (blockIdx.x * blockDim.x + threadIdx.x) * 4;
    if (base >= Ee) return;
    int4 s4v = *(const int4*)(ei + base);
    int4 d4v = *(const int4*)(ei + Ee + base);
    int ss[4] = {s4v.x, s4v.y, s4v.z, s4v.w};
    int dd[4] = {d4v.x, d4v.y, d4v.z, d4v.w};
#pragma unroll
    for (int j = 0; j < 4; j++) {
        int d = dd[j];
        int p = g_blkOff[d >> 10] + atomicAdd(&g_binCur[d], 1);
        g_esd[p] = make_int2(ss[j], d);
    }
}

// ---------------- kernel 1: node projections ----------------
__global__ __launch_bounds__(256) void node_proj_kernel(
    const float* __restrict__ x,
    const float* __restrict__ Win,  const float* __restrict__ bin,
    const float* __restrict__ Wlin)
{
    extern __shared__ __align__(16) char smem[];
    uint4*  sBF  = (uint4*)smem;                       // 8 x 512 uint4 = 64KB
    float2* sBin = (float2*)(smem + 65536);
    const int tid = threadIdx.x;

    build_bf4(sBF + 0 * 512, sBF + 1 * 512, Win,  tid, 256);
    build_bf4(sBF + 2 * 512, sBF + 3 * 512, Wlin, tid, 256);
    build_bf4(sBF + 4 * 512, sBF + 5 * 512, (const float*)g_WsA, tid, 256);
    build_bf4(sBF + 6 * 512, sBF + 7 * 512, (const float*)g_WdA, tid, 256);
    if (tid < 32) sBin[tid] = make_float2(bin[2 * tid], bin[2 * tid + 1]);
    __syncthreads();

    const int lane = tid & 31;
    const int g = lane >> 2, t = lane & 3;

    __half* outs[3] = { g_vh, g_Qh, g_Ph };

    const int nTiles = Nn / 16;  // 3125
    const int wStride = gridDim.x * 8;
    for (int tile = blockIdx.x * 8 + (tid >> 5); tile < nTiles; tile += wStride) {
        const int n0 = tile * 16;

        uint32_t Ah[16];
#pragma unroll
        for (int kt = 0; kt < 4; kt++)
#pragma unroll
            for (int half = 0; half < 2; half++)
#pragma unroll
                for (int h = 0; h < 2; h++) {
                    float2 xx = *(const float2*)&x[(n0 + g + 8 * h) * 64 + 16 * kt + 2 * t + 8 * half];
                    Ah[kt * 4 + h + 2 * half] = pack_f16x2(xx.x, xx.y);
                }

        float D[32];
#pragma unroll
        for (int i = 0; i < 32; i++) D[i] = 0.f;
        gemm2p(D, Ah, sBF + 0 * 512, sBF + 1 * 512, lane);

        uint32_t Ah2[16];
#pragma unroll
        for (int nt = 0; nt < 8; nt++) {
            float2 bb = sBin[4 * nt + t];
            int kt = nt >> 1, half = nt & 1, slot = kt * 4 + 2 * half;
            Ah2[slot]     = pack_f16x2(fmaxf(D[nt * 4 + 0] + bb.x, 0.f),
                                       fmaxf(D[nt * 4 + 1] + bb.y, 0.f));
            Ah2[slot + 1] = pack_f16x2(fmaxf(D[nt * 4 + 2] + bb.x, 0.f),
                                       fmaxf(D[nt * 4 + 3] + bb.y, 0.f));
        }

#pragma unroll
        for (int m = 0; m < 3; m++) {
#pragma unroll
            for (int i = 0; i < 32; i++) D[i] = 0.f;
            gemm2p(D, Ah2, sBF + (2 + 2 * m) * 512, sBF + (3 + 2 * m) * 512, lane);
            __half* o = outs[m];
#pragma unroll
            for (int ntp = 0; ntp < 4; ntp++) {
                int na = 2 * ntp, nb = na + 1;
                uint2 r0 = make_uint2(pack_f16x2(D[na * 4 + 0], D[na * 4 + 1]),
                                      pack_f16x2(D[nb * 4 + 0], D[nb * 4 + 1]));
                uint2 r8 = make_uint2(pack_f16x2(D[na * 4 + 2], D[na * 4 + 3]),
                                      pack_f16x2(D[nb * 4 + 2], D[nb * 4 + 3]));
                *(uint2*)(o + (n0 + g    ) * 64 + 16 * t + 4 * ntp) = r0;
                *(uint2*)(o + (n0 + g + 8) * 64 + 16 * t + 4 * ntp) = r8;
            }
        }
    }
}

// ---------------- kernel 2: fused edge kernel (dst-sorted, 2-level merged scatter) ----------------
#define ESM_WP1   24576
#define ESM_BP2   25600
#define ESM_CV    25856
#define ESM_BA2   26112
#define ESM_TOTAL 26624

__global__ __launch_bounds__(256, 2) void edge_fused_kernel(
    const float* __restrict__ pos,
    const float* __restrict__ Wp1, const float* __restrict__ bp1,
    const float* __restrict__ Wp2, const float* __restrict__ bp2,
    const float* __restrict__ Wa2, const float* __restrict__ ba2)
{
    extern __shared__ __align__(16) char smem[];
    uint4*  sBF  = (uint4*)smem;
    float4* sWp1 = (float4*)(smem + ESM_WP1);
    float2* sBp2 = (float2*)(smem + ESM_BP2);
    float2* sCv  = (float2*)(smem + ESM_CV);
    float2* sBa2 = (float2*)(smem + ESM_BA2);

    const int tid = threadIdx.x;
    build_bf4(sBF + 0 * 512, (uint4*)0, Wp2,                 tid, 256);
    build_bf4(sBF + 1 * 512, (uint4*)0, (const float*)g_WpA, tid, 256);
    build_bf4(sBF + 2 * 512, (uint4*)0, Wa2,                 tid, 256);
    if (tid < 64)
        sWp1[tid] = make_float4(Wp1[tid], Wp1[64 + tid], Wp1[128 + tid], bp1[tid]);
    if (tid < 32) {
        sBp2[tid] = make_float2(bp2[2 * tid], bp2[2 * tid + 1]);
        sCv[tid]  = make_float2(g_cvec[2 * tid], g_cvec[2 * tid + 1]);
        sBa2[tid] = make_float2(ba2[2 * tid], ba2[2 * tid + 1]);
    }
    __syncthreads();

    const int lane = tid & 31;
    const int g = lane >> 2, t = lane & 3;

    const uint4* bfP2h = sBF + 0 * 512;
    const uint4* bfPAh = sBF + 1 * 512;
    const uint4* bfA2h = sBF + 2 * 512;

    const int nTiles = Ee / 16;          // 50000
    const int wStride = gridDim.x * 8;

    int tile = blockIdx.x * 8 + (tid >> 5);

    int pS = 0, pD = 0;
    float pr0 = 0.f, pr1 = 0.f, pr2 = 0.f;
    if (tile < nTiles && lane < 16) {
        int2 sd = __ldg(&g_esd[tile * 16 + lane]);
        pS = sd.x; pD = sd.y;
        pr0 = __ldg(&pos[pD * 3 + 0]) - __ldg(&pos[pS * 3 + 0]);
        pr1 = __ldg(&pos[pD * 3 + 1]) - __ldg(&pos[pS * 3 + 1]);
        pr2 = __ldg(&pos[pD * 3 + 2]) - __ldg(&pos[pS * 3 + 2]);
    }

    for (; tile < nTiles; tile += wStride) {
        // thread owns CONSECUTIVE sorted edges 2g (row g) and 2g+1 (row g+8)
        int sn[2], dn[2];
        float rl[2][3];
#pragma unroll
        for (int h = 0; h < 2; h++) {
            int src = 2 * g + h;
            sn[h]   = __shfl_sync(0xffffffffu, pS, src);
            dn[h]   = __shfl_sync(0xffffffffu, pD, src);
            rl[h][0] = __shfl_sync(0xffffffffu, pr0, src);
            rl[h][1] = __shfl_sync(0xffffffffu, pr1, src);
            rl[h][2] = __shfl_sync(0xffffffffu, pr2, src);
        }
        const bool m01 = (dn[0] == dn[1]);

        const int tn = tile + wStride;
        int nS = 0, nD = 0;
        if (tn < nTiles && lane < 16) {
            int2 sd = __ldg(&g_esd[tn * 16 + lane]);
            nS = sd.x; nD = sd.y;
        }

        // hoist P/Q gathers (consumed after G2'); reuse P when dn equal
        uint4 P0a = __ldg((const uint4*)(g_Ph + dn[0] * 64 + 16 * t));
        uint4 P0b = __ldg((const uint4*)(g_Ph + dn[0] * 64 + 16 * t + 8));
        uint4 Q0a = __ldg((const uint4*)(g_Qh + sn[0] * 64 + 16 * t));
        uint4 Q0b = __ldg((const uint4*)(g_Qh + sn[0] * 64 + 16 * t + 8));
        uint4 P1a, P1b;
        if (!m01) {
            P1a = __ldg((const uint4*)(g_Ph + dn[1] * 64 + 16 * t));
            P1b = __ldg((const uint4*)(g_Ph + dn[1] * 64 + 16 * t + 8));
        } else { P1a = P0a; P1b = P0b; }
        uint4 Q1a = __ldg((const uint4*)(g_Qh + sn[1] * 64 + 16 * t));
        uint4 Q1b = __ldg((const uint4*)(g_Qh + sn[1] * 64 + 16 * t + 8));

        // stage 1: u = relu(rel @ Wp1 + bp1) -> A frags
        uint32_t Au[16];
#pragma unroll
        for (int kt = 0; kt < 4; kt++)
#pragma unroll
            for (int half = 0; half < 2; half++) {
                int c0 = 16 * kt + 2 * t + 8 * half;
                float4 w0 = sWp1[c0];
                float4 w1 = sWp1[c0 + 1];
#pragma unroll
                for (int h = 0; h < 2; h++) {
                    float u0 = fmaxf(fmaf(rl[h][2], w0.z, fmaf(rl[h][1], w0.y,
                               fmaf(rl[h][0], w0.x, w0.w))), 0.f);
                    float u1 = fmaxf(fmaf(rl[h][2], w1.z, fmaf(rl[h][1], w1.y,
                               fmaf(rl[h][0], w1.x, w1.w))), 0.f);
                    Au[kt * 4 + h + 2 * half] = pack_f16x2(u0, u1);
                }
            }

        // G2': h2_pre = u @ WpA
        float Dx[32];
#pragma unroll
        for (int i = 0; i < 32; i++) Dx[i] = 0.f;
        gemm1p(Dx, Au, bfPAh, lane);

        if (tn < nTiles && lane < 16) {
            pr0 = __ldg(&pos[nD * 3 + 0]) - __ldg(&pos[nS * 3 + 0]);
            pr1 = __ldg(&pos[nD * 3 + 1]) - __ldg(&pos[nS * 3 + 1]);
            pr2 = __ldg(&pos[nD * 3 + 2]) - __ldg(&pos[nS * 3 + 2]);
        }
        pS = nS; pD = nD;

        // epi-a: Dx += cvec + P[dn] - Q[sn]
        {
            uint32_t wP0[8] = {P0a.x, P0a.y, P0a.z, P0a.w, P0b.x, P0b.y, P0b.z, P0b.w};
            uint32_t wQ0[8] = {Q0a.x, Q0a.y, Q0a.z, Q0a.w, Q0b.x, Q0b.y, Q0b.z, Q0b.w};
            uint32_t wP1[8] = {P1a.x, P1a.y, P1a.z, P1a.w, P1b.x, P1b.y, P1b.z, P1b.w};
            uint32_t wQ1[8] = {Q1a.x, Q1a.y, Q1a.z, Q1a.w, Q1b.x, Q1b.y, Q1b.z, Q1b.w};
#pragma unroll
            for (int nt = 0; nt < 8; nt++) {
                float2 cv = sCv[4 * nt + t];
                float2 p0 = h2f2(wP0[nt]), q0 = h2f2(wQ0[nt]);
                float2 p1 = h2f2(wP1[nt]), q1 = h2f2(wQ1[nt]);
                Dx[nt * 4 + 0] += cv.x + p0.x - q0.x;
                Dx[nt * 4 + 1] += cv.y + p0.y - q0.y;
                Dx[nt * 4 + 2] += cv.x + p1.x - q1.x;
                Dx[nt * 4 + 3] += cv.y + p1.y - q1.y;
            }
        }

        // G1: delta_raw = u @ Wp2 (latency filler)
        float D1[32];
#pragma unroll
        for (int i = 0; i < 32; i++) D1[i] = 0.f;
        gemm1p(D1, Au, bfP2h, lane);

        uint32_t dltp[16];
#pragma unroll
        for (int nt = 0; nt < 8; nt++) {
            float2 bb = sBp2[4 * nt + t];
            dltp[2 * nt]     = pack_f16x2(D1[nt * 4 + 0] + bb.x, D1[nt * 4 + 1] + bb.y);
            dltp[2 * nt + 1] = pack_f16x2(D1[nt * 4 + 2] + bb.x, D1[nt * 4 + 3] + bb.y);
        }

        // epi-b: h2 = relu(Dx) -> A frags
#pragma unroll
        for (int nt = 0; nt < 8; nt++) {
            int kt = nt >> 1, half = nt & 1, slot = kt * 4 + 2 * half;
            Au[slot]     = pack_f16x2(fmaxf(Dx[nt * 4 + 0], 0.f), fmaxf(Dx[nt * 4 + 1], 0.f));
            Au[slot + 1] = pack_f16x2(fmaxf(Dx[nt * 4 + 2], 0.f), fmaxf(Dx[nt * 4 + 3], 0.f));
        }

        // v gathers (covered by G3)
        uint4 v0a = __ldg((const uint4*)(g_vh + sn[0] * 64 + 16 * t));
        uint4 v0b = __ldg((const uint4*)(g_vh + sn[0] * 64 + 16 * t + 8));
        uint4 v1a = __ldg((const uint4*)(g_vh + sn[1] * 64 + 16 * t));
        uint4 v1b = __ldg((const uint4*)(g_vh + sn[1] * 64 + 16 * t + 8));

        // G3: logits = h2 @ Wa2
#pragma unroll
        for (int i = 0; i < 32; i++) Dx[i] = 0.f;
        gemm1p(Dx, Au, bfA2h, lane);

        // final epi with 2-level hierarchical dst-merge
        uint32_t wv0[8] = {v0a.x, v0a.y, v0a.z, v0a.w, v0b.x, v0b.y, v0b.z, v0b.w};
        uint32_t wv1[8] = {v1a.x, v1a.y, v1a.z, v1a.w, v1b.x, v1b.y, v1b.z, v1b.w};
        float* sp_ = (float*)g_s4;
        float* ap_ = (float*)g_acc4;
        float ms[16], ma[16];
#pragma unroll
        for (int ntp = 0; ntp < 4; ntp++) {
            int na = 2 * ntp, nb = na + 1;
            float2 ba_a = sBa2[4 * na + t], ba_b = sBa2[4 * nb + t];
            float2 va0 = h2f2(wv0[na]), vb0 = h2f2(wv0[nb]);
            float2 va1 = h2f2(wv1[na]), vb1 = h2f2(wv1[nb]);
            float2 dna0 = h2f2(dltp[2 * na]),     dnb0 = h2f2(dltp[2 * nb]);
            float2 dna1 = h2f2(dltp[2 * na + 1]), dnb1 = h2f2(dltp[2 * nb + 1]);
            float e00 = __expf(Dx[na * 4 + 0] + ba_a.x);
            float e01 = __expf(Dx[na * 4 + 1] + ba_a.y);
            float e02 = __expf(Dx[nb * 4 + 0] + ba_b.x);
            float e03 = __expf(Dx[nb * 4 + 1] + ba_b.y);
            float a00 = e00 * (va0.x + dna0.x);
            float a01 = e01 * (va0.y + dna0.y);
            float a02 = e02 * (vb0.x + dnb0.x);
            float a03 = e03 * (vb0.y + dnb0.y);
            float e10 = __expf(Dx[na * 4 + 2] + ba_a.x);
            float e11 = __expf(Dx[na * 4 + 3] + ba_a.y);
            float e12 = __expf(Dx[nb * 4 + 2] + ba_b.x);
            float e13 = __expf(Dx[nb * 4 + 3] + ba_b.y);
            float a10 = e10 * (va1.x + dna1.x);
            float a11 = e11 * (va1.y + dna1.y);
            float a12 = e12 * (vb1.x + dnb1.x);
            float a13 = e13 * (vb1.y + dnb1.y);
            if (m01) {
                ms[4*ntp+0] = e00 + e10; ms[4*ntp+1] = e01 + e11;
                ms[4*ntp+2] = e02 + e12; ms[4*ntp+3] = e03 + e13;
                ma[4*ntp+0] = a00 + a10; ma[4*ntp+1] = a01 + a11;
                ma[4*ntp+2] = a02 + a12; ma[4*ntp+3] = a03 + a13;
            } else {
                ms[4*ntp+0] = e00; ms[4*ntp+1] = e01;
                ms[4*ntp+2] = e02; ms[4*ntp+3] = e03;
                ma[4*ntp+0] = a00; ma[4*ntp+1] = a01;
                ma[4*ntp+2] = a02; ma[4*ntp+3] = a03;
                int off1 = dn[1] * 64 + 16 * t + 4 * ntp;
                red4((float4*)(sp_ + off1), e10, e11, e12, e13);
                red4((float4*)(ap_ + off1), a10, a11, a12, a13);
            }
        }
        // level 1: xor-4 (merge 4 consecutive edges)
        unsigned bal = __ballot_sync(0xffffffffu, m01);
        bool pm01 = (bal >> (lane ^ 4)) & 1u;
        int pdn0 = __shfl_xor_sync(0xffffffffu, dn[0], 4);
        bool joint  = m01 && pm01 && (dn[0] == pdn0);
        bool absorb = joint && ((g & 1) == 0);
        bool dead   = joint && ((g & 1) == 1);
#pragma unroll
        for (int i = 0; i < 16; i++) {
            float pv = __shfl_xor_sync(0xffffffffu, ms[i], 4);
            if (absorb) ms[i] += pv;
        }
#pragma unroll
        for (int i = 0; i < 16; i++) {
            float pv = __shfl_xor_sync(0xffffffffu, ma[i], 4);
            if (absorb) ma[i] += pv;
        }
        // level 2: xor-8 (merge 8 consecutive edges)
        unsigned bal4 = __ballot_sync(0xffffffffu, joint);
        bool pjoint = (bal4 >> (lane ^ 8)) & 1u;
        int p8dn = __shfl_xor_sync(0xffffffffu, dn[0], 8);
        bool joint8  = joint && pjoint && (dn[0] == p8dn);
        bool absorb8 = joint8 && ((g & 2) == 0);
        bool dead8   = joint8 && ((g & 2) != 0);
#pragma unroll
        for (int i = 0; i < 16; i++) {
            float pv = __shfl_xor_sync(0xffffffffu, ms[i], 8);
            if (absorb8) ms[i] += pv;
        }
#pragma unroll
        for (int i = 0; i < 16; i++) {
            float pv = __shfl_xor_sync(0xffffffffu, ma[i], 8);
            if (absorb8) ma[i] += pv;
        }
        if (!dead && !dead8) {
            int off0 = dn[0] * 64 + 16 * t;
#pragma unroll
            for (int q = 0; q < 4; q++) {
                red4((float4*)(sp_ + off0 + 4 * q), ms[4*q], ms[4*q+1], ms[4*q+2], ms[4*q+3]);
                red4((float4*)(ap_ + off0 + 4 * q), ma[4*q], ma[4*q+1], ma[4*q+2], ma[4*q+3]);
            }
        }
    }
}

// ---------------- kernel 3: normalize + lin_out + relu (mma) ----------------
__global__ __launch_bounds__(256) void node_out_kernel(
    const float* __restrict__ Wout, const float* __restrict__ bout,
    float* __restrict__ out)
{
    extern __shared__ __align__(16) char smem[];
    uint4*  sBF  = (uint4*)smem;                  // Wout hi + lo = 16KB
    float2* sB   = (float2*)(smem + 16384);
    const int tid = threadIdx.x;
    build_bf4(sBF, sBF + 512, Wout, tid, 256);
    if (tid < 32) sB[tid] = make_float2(bout[2 * tid], bout[2 * tid + 1]);
    __syncthreads();

    const int lane = tid & 31;
    const int g = lane >> 2, t = lane & 3;
    const float* accp = (const float*)g_acc4;
    const float* ssp  = (const float*)g_s4;

    const int nTiles = Nn / 16;  // 3125
    const int wStride = gridDim.x * 8;
    for (int tile = blockIdx.x * 8 + (tid >> 5); tile < nTiles; tile += wStride) {
        const int n0 = tile * 16;

        float rg0[16], rg1[16];
#pragma unroll
        for (int q = 0; q < 4; q++) {
            float4 a0 = *(const float4*)(accp + (n0 + g) * 64 + 16 * t + 4 * q);
            float4 s0 = *(const float4*)(ssp  + (n0 + g) * 64 + 16 * t + 4 * q);
            rg0[4 * q + 0] = a0.x / (s0.x + 1e-16f);
            rg0[4 * q + 1] = a0.y / (s0.y + 1e-16f);
            rg0[4 * q + 2] = a0.z / (s0.z + 1e-16f);
            rg0[4 * q + 3] = a0.w / (s0.w + 1e-16f);
            float4 a1 = *(const float4*)(accp + (n0 + g + 8) * 64 + 16 * t + 4 * q);
            float4 s1 = *(const float4*)(ssp  + (n0 + g + 8) * 64 + 16 * t + 4 * q);
            rg1[4 * q + 0] = a1.x / (s1.x + 1e-16f);
            rg1[4 * q + 1] = a1.y / (s1.y + 1e-16f);
            rg1[4 * q + 2] = a1.z / (s1.z + 1e-16f);
            rg1[4 * q + 3] = a1.w / (s1.w + 1e-16f);
        }

        uint32_t Ah[16], Al[16];
#pragma unroll
        for (int nt = 0; nt < 8; nt++) {
            int kt = nt >> 1, half = nt & 1, slot = kt * 4 + 2 * half;
            pack_hl_f16(rg0[2 * nt], rg0[2 * nt + 1], Ah[slot],     Al[slot]);
            pack_hl_f16(rg1[2 * nt], rg1[2 * nt + 1], Ah[slot + 1], Al[slot + 1]);
        }

        float D[32];
#pragma unroll
        for (int i = 0; i < 32; i++) D[i] = 0.f;
        gemm3p(D, Ah, Al, sBF, sBF + 512, lane);

#pragma unroll
        for (int nt = 0; nt < 8; nt++) {
            int c0 = 8 * nt + 2 * t;
            float2 bb = sB[4 * nt + t];
            *(float2*)&out[(n0 + g    ) * 64 + c0] =
                make_float2(fmaxf(D[nt * 4 + 0] + bb.x, 0.f),
                            fmaxf(D[nt * 4 + 1] + bb.y, 0.f));
            *(float2*)&out[(n0 + g + 8) * 64 + c0] =
                make_float2(fmaxf(D[nt * 4 + 2] + bb.x, 0.f),
                            fmaxf(D[nt * 4 + 3] + bb.y, 0.f));
        }
    }
}

// ---------------- launch ----------------
extern "C" void kernel_launch(void* const* d_in, const int* in_sizes, int n_in,
                              void* d_out, int out_size)
{
    const float* x    = (const float*)d_in[0];
    const float* pos  = (const float*)d_in[1];
    const int*   ei   = (const int*)  d_in[2];
    const float* Win  = (const float*)d_in[3];
    const float* bin  = (const float*)d_in[4];
    const float* Wlin = (const float*)d_in[5];
    const float* Wsrc = (const float*)d_in[6];
    const float* Wdst = (const float*)d_in[7];
    const float* Wp1  = (const float*)d_in[8];
    const float* bp1  = (const float*)d_in[9];
    const float* Wp2  = (const float*)d_in[10];
    const float* bp2  = (const float*)d_in[11];
    const float* Wa1  = (const float*)d_in[12];
    const float* ba1  = (const float*)d_in[13];
    const float* Wa2  = (const float*)d_in[14];
    const float* ba2  = (const float*)d_in[15];
    const float* Wout = (const float*)d_in[16];
    const float* bout = (const float*)d_in[17];

    const int projSmem = 65536 + 256;
    const int outSmem  = 16384 + 256;
    cudaFuncSetAttribute(node_proj_kernel,  cudaFuncAttributeMaxDynamicSharedMemorySize, projSmem);
    cudaFuncSetAttribute(edge_fused_kernel, cudaFuncAttributeMaxDynamicSharedMemorySize, ESM_TOTAL);
    cudaFuncSetAttribute(node_out_kernel,   cudaFuncAttributeMaxDynamicSharedMemorySize, outSmem);

    init_kernel<<<(Nn * 16 + 255) / 256, 256>>>();
    hist_kernel<<<(Ee + 255) / 256, 256>>>(ei);
    scanA_kernel<<<(Nn + 1023) / 1024, 1024>>>();
    scanB_kernel<<<1, 32>>>();
    scatter_kernel<<<(Ee / 4 + 255) / 256, 256>>>(ei);
    fold_kernel<<<48, 256>>>(Wsrc, Wdst, Wp2, Wa1, bp2, ba1);
    node_proj_kernel<<<391, 256, projSmem>>>(x, Win, bin, Wlin);
    edge_fused_kernel<<<296, 256, ESM_TOTAL>>>(pos, Wp1, bp1, Wp2, bp2, Wa2, ba2);
    node_out_kernel<<<391, 256, outSmem>>>(Wout, bout, (float*)d_out);
}

// round 15
// speedup vs baseline: 1.1731x; 1.0014x over previous
#include <cuda_runtime.h>
#include <cuda_fp16.h>
#include <cstdint>
#include <cstddef>

#define Nn 50000
#define Ee 800000

// ---------------- scratch (static device globals; no allocation) ----------------
__device__ float4 g_s4  [Nn * 16];
__device__ float4 g_acc4[Nn * 16];
__device__ __align__(16) __half g_vh[Nn * 64];
__device__ __align__(16) __half g_Qh[Nn * 64];
__device__ __align__(16) __half g_Ph[Nn * 64];
__device__ float g_WsA[4096];
__device__ float g_WdA[4096];
__device__ float g_WpA[4096];
__device__ float g_cvec[64];
// dst-sort machinery
__device__ int  g_binCnt[Nn];
__device__ int  g_binCur[Nn];
__device__ int  g_blkSum[64];
__device__ int2 g_esd[Ee];     // sorted (src,dst) records

// ---------------- helpers ----------------
__device__ __forceinline__ uint32_t pack_f16x2(float a, float b) {
    uint32_t w;
    asm("cvt.rn.f16x2.f32 %0, %1, %2;" : "=r"(w) : "f"(b), "f"(a));  // lo=a, hi=b
    return w;
}
__device__ __forceinline__ void pack_hl_f16(float a, float b, uint32_t& h, uint32_t& l) {
    asm("cvt.rn.f16x2.f32 %0, %1, %2;" : "=r"(h) : "f"(b), "f"(a));
    __half2 h2 = *reinterpret_cast<__half2*>(&h);
    float la = a - __half2float(h2.x);
    float lb = b - __half2float(h2.y);
    asm("cvt.rn.f16x2.f32 %0, %1, %2;" : "=r"(l) : "f"(lb), "f"(la));
}
__device__ __forceinline__ float2 h2f2(uint32_t w) {
    __half2 h = *reinterpret_cast<__half2*>(&w);
    return make_float2(__half2float(h.x), __half2float(h.y));
}
__device__ __forceinline__ void red4(float4* p, float a, float b, float c, float d) {
    asm volatile("red.global.add.v4.f32 [%0], {%1, %2, %3, %4};"
                 :: "l"(p), "f"(a), "f"(b), "f"(c), "f"(d) : "memory");
}
__device__ __forceinline__ void mma_f16(float* d, const uint32_t* a, uint32_t b0, uint32_t b1) {
    asm volatile(
        "mma.sync.aligned.m16n8k16.row.col.f32.f16.f16.f32 "
        "{%0,%1,%2,%3},{%4,%5,%6,%7},{%8,%9},{%0,%1,%2,%3};"
        : "+f"(d[0]), "+f"(d[1]), "+f"(d[2]), "+f"(d[3])
        : "r"(a[0]), "r"(a[1]), "r"(a[2]), "r"(a[3]), "r"(b0), "r"(b1));
}
__device__ __forceinline__ void gemm1p(float* D, const uint32_t* Ah,
                                       const uint4* __restrict__ bf, int lane) {
#pragma unroll
    for (int kt = 0; kt < 4; kt++)
#pragma unroll
        for (int ntp = 0; ntp < 4; ntp++) {
            uint4 b = bf[(kt * 4 + ntp) * 32 + lane];
            mma_f16(D + (2 * ntp)     * 4, Ah + kt * 4, b.x, b.y);
            mma_f16(D + (2 * ntp + 1) * 4, Ah + kt * 4, b.z, b.w);
        }
}
__device__ __forceinline__ void gemm2p(float* D, const uint32_t* Ah,
                                       const uint4* __restrict__ bfH,
                                       const uint4* __restrict__ bfL, int lane) {
#pragma unroll
    for (int kt = 0; kt < 4; kt++)
#pragma unroll
        for (int ntp = 0; ntp < 4; ntp++) {
            uint4 bh = bfH[(kt * 4 + ntp) * 32 + lane];
            mma_f16(D + (2 * ntp)     * 4, Ah + kt * 4, bh.x, bh.y);
            mma_f16(D + (2 * ntp + 1) * 4, Ah + kt * 4, bh.z, bh.w);
            uint4 bl = bfL[(kt * 4 + ntp) * 32 + lane];
            mma_f16(D + (2 * ntp)     * 4, Ah + kt * 4, bl.x, bl.y);
            mma_f16(D + (2 * ntp + 1) * 4, Ah + kt * 4, bl.z, bl.w);
        }
}
__device__ __forceinline__ void gemm3p(float* D, const uint32_t* Ah, const uint32_t* Al,
                                       const uint4* __restrict__ bfH,
                                       const uint4* __restrict__ bfL, int lane) {
#pragma unroll
    for (int kt = 0; kt < 4; kt++)
#pragma unroll
        for (int ntp = 0; ntp < 4; ntp++) {
            uint4 bh = bfH[(kt * 4 + ntp) * 32 + lane];
            mma_f16(D + (2 * ntp)     * 4, Ah + kt * 4, bh.x, bh.y);
            mma_f16(D + (2 * ntp + 1) * 4, Ah + kt * 4, bh.z, bh.w);
            mma_f16(D + (2 * ntp)     * 4, Al + kt * 4, bh.x, bh.y);
            mma_f16(D + (2 * ntp + 1) * 4, Al + kt * 4, bh.z, bh.w);
            uint4 bl = bfL[(kt * 4 + ntp) * 32 + lane];
            mma_f16(D + (2 * ntp)     * 4, Ah + kt * 4, bl.x, bl.y);
            mma_f16(D + (2 * ntp + 1) * 4, Ah + kt * 4, bl.z, bl.w);
        }
}

__device__ __forceinline__ void build_bf4(uint4* dstH, uint4* dstL,
                                          const float* __restrict__ W,
                                          int tid, int nth) {
    for (int i = tid; i < 1024; i += nth) {
        int kt = i >> 8, nt = (i >> 5) & 7, lane = i & 31;
        int g = lane >> 2, t = lane & 3;
        int col = 8 * nt + g;
        int k0  = 16 * kt + 2 * t;
        float w00 = W[(k0    ) * 64 + col];
        float w01 = W[(k0 + 1) * 64 + col];
        float w10 = W[(k0 + 8) * 64 + col];
        float w11 = W[(k0 + 9) * 64 + col];
        uint32_t h0, l0, h1, l1;
        pack_hl_f16(w00, w01, h0, l0);
        pack_hl_f16(w10, w11, h1, l1);
        uint32_t* pH = (uint32_t*)&dstH[(kt * 4 + (nt >> 1)) * 32 + lane];
        int sub = (nt & 1) * 2;
        pH[sub] = h0; pH[sub + 1] = h1;
        if (dstL) {
            uint32_t* pL = (uint32_t*)&dstL[(kt * 4 + (nt >> 1)) * 32 + lane];
            pL[sub] = l0; pL[sub + 1] = l1;
        }
    }
}

// ---------------- kernel -1: fold weight products (fp32) ----------------
__global__ __launch_bounds__(256) void fold_kernel(
    const float* __restrict__ Wsrc, const float* __restrict__ Wdst,
    const float* __restrict__ Wp2,  const float* __restrict__ Wa1,
    const float* __restrict__ bp2,  const float* __restrict__ ba1)
{
    int gid = blockIdx.x * blockDim.x + threadIdx.x;
    if (gid < 3 * 4096) {
        int m = gid >> 12;
        int idx = gid & 4095;
        int i = idx >> 6, j = idx & 63;
        const float* A = (m == 0) ? Wsrc : (m == 1) ? Wdst : Wp2;
        float s = 0.f;
        for (int k = 0; k < 64; k++) s = fmaf(A[i * 64 + k], Wa1[k * 64 + j], s);
        float* O = (m == 0) ? g_WsA : (m == 1) ? g_WdA : g_WpA;
        O[idx] = s;
    }
    if (gid < 64) {
        float s = ba1[gid];
        for (int k = 0; k < 64; k++) s = fmaf(bp2[k], Wa1[k * 64 + gid], s);
        g_cvec[gid] = s;
    }
}

// ---------------- kernel 0a: zero histogram bins ----------------
__global__ __launch_bounds__(256) void zero_cnt_kernel() {
    int i = blockIdx.x * blockDim.x + threadIdx.x;
    if (i < Nn) g_binCnt[i] = 0;
}

// ---------------- kernel 0b: zero accumulators + dst histogram (Nn*16 == Ee) ----------------
__global__ __launch_bounds__(256) void init_hist_kernel(const int* __restrict__ ei) {
    int i = blockIdx.x * blockDim.x + threadIdx.x;   // grid covers exactly 800000
    g_s4[i]   = make_float4(0.f, 0.f, 0.f, 0.f);
    g_acc4[i] = make_float4(0.f, 0.f, 0.f, 0.f);
    atomicAdd(&g_binCnt[ei[Ee + i]], 1);
}

// block-local exclusive scan over 1024 bins; block total to g_blkSum
__global__ __launch_bounds__(1024) void scanA_kernel() {
    __shared__ int wsum[32];
    int i = blockIdx.x * 1024 + threadIdx.x;
    int lane = threadIdx.x & 31, wid = threadIdx.x >> 5;
    int v = (i < Nn) ? g_binCnt[i] : 0;
    int incl = v;
#pragma unroll
    for (int o = 1; o < 32; o <<= 1) {
        int u = __shfl_up_sync(0xffffffffu, incl, o);
        if (lane >= o) incl += u;
    }
    if (lane == 31) wsum[wid] = incl;
    __syncthreads();
    if (wid == 0) {
        int w = wsum[lane];
        int wi = w;
#pragma unroll
        for (int o = 1; o < 32; o <<= 1) {
            int u = __shfl_up_sync(0xffffffffu, wi, o);
            if (lane >= o) wi += u;
        }
        wsum[lane] = wi - w;
    }
    __syncthreads();
    int excl = incl - v + wsum[wid];
    if (i < Nn) g_binCur[i] = excl;
    if (threadIdx.x == 1023) g_blkSum[blockIdx.x] = excl + v;
}

// ILP-4 scatter; each block re-derives the 49-entry block-offset prefix itself
__global__ __launch_bounds__(256) void scatter_kernel(const int* __restrict__ ei) {
    __shared__ int sOff[64];
    const int nBlk = (Nn + 1023) / 1024;  // 49
    if (threadIdx.x < 32) {
        int lane = threadIdx.x;
        int a = (lane < nBlk) ? g_blkSum[lane] : 0;
        int b = (lane + 32 < nBlk) ? g_blkSum[lane + 32] : 0;
        int ia = a, ib = b;
#pragma unroll
        for (int o = 1; o < 32; o <<= 1) {
            int u = __shfl_up_sync(0xffffffffu, ia, o);
            if (lane >= o) ia += u;
            int u2 = __shfl_up_sync(0xffffffffu, ib, o);
            if (lane >= o) ib += u2;
        }
        int totA = __shfl_sync(0xffffffffu, ia, 31);
        sOff[lane]      = ia - a;
        sOff[lane + 32] = totA + ib - b;
    }
    __syncthreads();
    int base = (blockIdx.x * blockDim.x + threadIdx.x) * 4;
    if (base >= Ee) return;
    int4 s4v = *(const int4*)(ei + base);
    int4 d4v = *(const int4*)(ei + Ee + base);
    int ss[4] = {s4v.x, s4v.y, s4v.z, s4v.w};
    int dd[4] = {d4v.x, d4v.y, d4v.z, d4v.w};
#pragma unroll
    for (int j = 0; j < 4; j++) {
        int d = dd[j];
        int p = sOff[d >> 10] + atomicAdd(&g_binCur[d], 1);
        g_esd[p] = make_int2(ss[j], d);
    }
}

// ---------------- kernel 1: node projections ----------------
__global__ __launch_bounds__(256) void node_proj_kernel(
    const float* __restrict__ x,
    const float* __restrict__ Win,  const float* __restrict__ bin,
    const float* __restrict__ Wlin)
{
    extern __shared__ __align__(16) char smem[];
    uint4*  sBF  = (uint4*)smem;                       // 8 x 512 uint4 = 64KB
    float2* sBin = (float2*)(smem + 65536);
    const int tid = threadIdx.x;

    build_bf4(sBF + 0 * 512, sBF + 1 * 512, Win,  tid, 256);
    build_bf4(sBF + 2 * 512, sBF + 3 * 512, Wlin, tid, 256);
    build_bf4(sBF + 4 * 512, sBF + 5 * 512, (const float*)g_WsA, tid, 256);
    build_bf4(sBF + 6 * 512, sBF + 7 * 512, (const float*)g_WdA, tid, 256);
    if (tid < 32) sBin[tid] = make_float2(bin[2 * tid], bin[2 * tid + 1]);
    __syncthreads();

    const int lane = tid & 31;
    const int g = lane >> 2, t = lane & 3;

    __half* outs[3] = { g_vh, g_Qh, g_Ph };

    const int nTiles = Nn / 16;  // 3125
    const int wStride = gridDim.x * 8;
    for (int tile = blockIdx.x * 8 + (tid >> 5); tile < nTiles; tile += wStride) {
        const int n0 = tile * 16;

        uint32_t Ah[16];
#pragma unroll
        for (int kt = 0; kt < 4; kt++)
#pragma unroll
            for (int half = 0; half < 2; half++)
#pragma unroll
                for (int h = 0; h < 2; h++) {
                    float2 xx = *(const float2*)&x[(n0 + g + 8 * h) * 64 + 16 * kt + 2 * t + 8 * half];
                    Ah[kt * 4 + h + 2 * half] = pack_f16x2(xx.x, xx.y);
                }

        float D[32];
#pragma unroll
        for (int i = 0; i < 32; i++) D[i] = 0.f;
        gemm2p(D, Ah, sBF + 0 * 512, sBF + 1 * 512, lane);

        uint32_t Ah2[16];
#pragma unroll
        for (int nt = 0; nt < 8; nt++) {
            float2 bb = sBin[4 * nt + t];
            int kt = nt >> 1, half = nt & 1, slot = kt * 4 + 2 * half;
            Ah2[slot]     = pack_f16x2(fmaxf(D[nt * 4 + 0] + bb.x, 0.f),
                                       fmaxf(D[nt * 4 + 1] + bb.y, 0.f));
            Ah2[slot + 1] = pack_f16x2(fmaxf(D[nt * 4 + 2] + bb.x, 0.f),
                                       fmaxf(D[nt * 4 + 3] + bb.y, 0.f));
        }

#pragma unroll
        for (int m = 0; m < 3; m++) {
#pragma unroll
            for (int i = 0; i < 32; i++) D[i] = 0.f;
            gemm2p(D, Ah2, sBF + (2 + 2 * m) * 512, sBF + (3 + 2 * m) * 512, lane);
            __half* o = outs[m];
#pragma unroll
            for (int ntp = 0; ntp < 4; ntp++) {
                int na = 2 * ntp, nb = na + 1;
                uint2 r0 = make_uint2(pack_f16x2(D[na * 4 + 0], D[na * 4 + 1]),
                                      pack_f16x2(D[nb * 4 + 0], D[nb * 4 + 1]));
                uint2 r8 = make_uint2(pack_f16x2(D[na * 4 + 2], D[na * 4 + 3]),
                                      pack_f16x2(D[nb * 4 + 2], D[nb * 4 + 3]));
                *(uint2*)(o + (n0 + g    ) * 64 + 16 * t + 4 * ntp) = r0;
                *(uint2*)(o + (n0 + g + 8) * 64 + 16 * t + 4 * ntp) = r8;
            }
        }
    }
}

// ---------------- kernel 2: fused edge kernel (dst-sorted, 2-level merged scatter) ----------------
#define ESM_WP1   24576
#define ESM_BP2   25600
#define ESM_CV    25856
#define ESM_BA2   26112
#define ESM_TOTAL 26624

__global__ __launch_bounds__(256, 2) void edge_fused_kernel(
    const float* __restrict__ pos,
    const float* __restrict__ Wp1, const float* __restrict__ bp1,
    const float* __restrict__ Wp2, const float* __restrict__ bp2,
    const float* __restrict__ Wa2, const float* __restrict__ ba2)
{
    extern __shared__ __align__(16) char smem[];
    uint4*  sBF  = (uint4*)smem;
    float4* sWp1 = (float4*)(smem + ESM_WP1);
    float2* sBp2 = (float2*)(smem + ESM_BP2);
    float2* sCv  = (float2*)(smem + ESM_CV);
    float2* sBa2 = (float2*)(smem + ESM_BA2);

    const int tid = threadIdx.x;
    build_bf4(sBF + 0 * 512, (uint4*)0, Wp2,                 tid, 256);
    build_bf4(sBF + 1 * 512, (uint4*)0, (const float*)g_WpA, tid, 256);
    build_bf4(sBF + 2 * 512, (uint4*)0, Wa2,                 tid, 256);
    if (tid < 64)
        sWp1[tid] = make_float4(Wp1[tid], Wp1[64 + tid], Wp1[128 + tid], bp1[tid]);
    if (tid < 32) {
        sBp2[tid] = make_float2(bp2[2 * tid], bp2[2 * tid + 1]);
        sCv[tid]  = make_float2(g_cvec[2 * tid], g_cvec[2 * tid + 1]);
        sBa2[tid] = make_float2(ba2[2 * tid], ba2[2 * tid + 1]);
    }
    __syncthreads();

    const int lane = tid & 31;
    const int g = lane >> 2, t = lane & 3;

    const uint4* bfP2h = sBF + 0 * 512;
    const uint4* bfPAh = sBF + 1 * 512;
    const uint4* bfA2h = sBF + 2 * 512;

    const int nTiles = Ee / 16;          // 50000
    const int wStride = gridDim.x * 8;

    int tile = blockIdx.x * 8 + (tid >> 5);

    int pS = 0, pD = 0;
    float pr0 = 0.f, pr1 = 0.f, pr2 = 0.f;
    if (tile < nTiles && lane < 16) {
        int2 sd = __ldg(&g_esd[tile * 16 + lane]);
        pS = sd.x; pD = sd.y;
        pr0 = __ldg(&pos[pD * 3 + 0]) - __ldg(&pos[pS * 3 + 0]);
        pr1 = __ldg(&pos[pD * 3 + 1]) - __ldg(&pos[pS * 3 + 1]);
        pr2 = __ldg(&pos[pD * 3 + 2]) - __ldg(&pos[pS * 3 + 2]);
    }

    for (; tile < nTiles; tile += wStride) {
        // thread owns CONSECUTIVE sorted edges 2g (row g) and 2g+1 (row g+8)
        int sn[2], dn[2];
        float rl[2][3];
#pragma unroll
        for (int h = 0; h < 2; h++) {
            int src = 2 * g + h;
            sn[h]   = __shfl_sync(0xffffffffu, pS, src);
            dn[h]   = __shfl_sync(0xffffffffu, pD, src);
            rl[h][0] = __shfl_sync(0xffffffffu, pr0, src);
            rl[h][1] = __shfl_sync(0xffffffffu, pr1, src);
            rl[h][2] = __shfl_sync(0xffffffffu, pr2, src);
        }
        const bool m01 = (dn[0] == dn[1]);

        const int tn = tile + wStride;
        int nS = 0, nD = 0;
        if (tn < nTiles && lane < 16) {
            int2 sd = __ldg(&g_esd[tn * 16 + lane]);
            nS = sd.x; nD = sd.y;
        }

        // hoist P/Q gathers (consumed after G2'); reuse P when dn equal
        uint4 P0a = __ldg((const uint4*)(g_Ph + dn[0] * 64 + 16 * t));
        uint4 P0b = __ldg((const uint4*)(g_Ph + dn[0] * 64 + 16 * t + 8));
        uint4 Q0a = __ldg((const uint4*)(g_Qh + sn[0] * 64 + 16 * t));
        uint4 Q0b = __ldg((const uint4*)(g_Qh + sn[0] * 64 + 16 * t + 8));
        uint4 P1a, P1b;
        if (!m01) {
            P1a = __ldg((const uint4*)(g_Ph + dn[1] * 64 + 16 * t));
            P1b = __ldg((const uint4*)(g_Ph + dn[1] * 64 + 16 * t + 8));
        } else { P1a = P0a; P1b = P0b; }
        uint4 Q1a = __ldg((const uint4*)(g_Qh + sn[1] * 64 + 16 * t));
        uint4 Q1b = __ldg((const uint4*)(g_Qh + sn[1] * 64 + 16 * t + 8));

        // stage 1: u = relu(rel @ Wp1 + bp1) -> A frags
        uint32_t Au[16];
#pragma unroll
        for (int kt = 0; kt < 4; kt++)
#pragma unroll
            for (int half = 0; half < 2; half++) {
                int c0 = 16 * kt + 2 * t + 8 * half;
                float4 w0 = sWp1[c0];
                float4 w1 = sWp1[c0 + 1];
#pragma unroll
                for (int h = 0; h < 2; h++) {
                    float u0 = fmaxf(fmaf(rl[h][2], w0.z, fmaf(rl[h][1], w0.y,
                               fmaf(rl[h][0], w0.x, w0.w))), 0.f);
                    float u1 = fmaxf(fmaf(rl[h][2], w1.z, fmaf(rl[h][1], w1.y,
                               fmaf(rl[h][0], w1.x, w1.w))), 0.f);
                    Au[kt * 4 + h + 2 * half] = pack_f16x2(u0, u1);
                }
            }

        // G2': h2_pre = u @ WpA
        float Dx[32];
#pragma unroll
        for (int i = 0; i < 32; i++) Dx[i] = 0.f;
        gemm1p(Dx, Au, bfPAh, lane);

        if (tn < nTiles && lane < 16) {
            pr0 = __ldg(&pos[nD * 3 + 0]) - __ldg(&pos[nS * 3 + 0]);
            pr1 = __ldg(&pos[nD * 3 + 1]) - __ldg(&pos[nS * 3 + 1]);
            pr2 = __ldg(&pos[nD * 3 + 2]) - __ldg(&pos[nS * 3 + 2]);
        }
        pS = nS; pD = nD;

        // epi-a: Dx += cvec + P[dn] - Q[sn]
        {
            uint32_t wP0[8] = {P0a.x, P0a.y, P0a.z, P0a.w, P0b.x, P0b.y, P0b.z, P0b.w};
            uint32_t wQ0[8] = {Q0a.x, Q0a.y, Q0a.z, Q0a.w, Q0b.x, Q0b.y, Q0b.z, Q0b.w};
            uint32_t wP1[8] = {P1a.x, P1a.y, P1a.z, P1a.w, P1b.x, P1b.y, P1b.z, P1b.w};
            uint32_t wQ1[8] = {Q1a.x, Q1a.y, Q1a.z, Q1a.w, Q1b.x, Q1b.y, Q1b.z, Q1b.w};
#pragma unroll
            for (int nt = 0; nt < 8; nt++) {
                float2 cv = sCv[4 * nt + t];
                float2 p0 = h2f2(wP0[nt]), q0 = h2f2(wQ0[nt]);
                float2 p1 = h2f2(wP1[nt]), q1 = h2f2(wQ1[nt]);
                Dx[nt * 4 + 0] += cv.x + p0.x - q0.x;
                Dx[nt * 4 + 1] += cv.y + p0.y - q0.y;
                Dx[nt * 4 + 2] += cv.x + p1.x - q1.x;
                Dx[nt * 4 + 3] += cv.y + p1.y - q1.y;
            }
        }

        // G1: delta_raw = u @ Wp2 (latency filler)
        float D1[32];
#pragma unroll
        for (int i = 0; i < 32; i++) D1[i] = 0.f;
        gemm1p(D1, Au, bfP2h, lane);

        uint32_t dltp[16];
#pragma unroll
        for (int nt = 0; nt < 8; nt++) {
            float2 bb = sBp2[4 * nt + t];
            dltp[2 * nt]     = pack_f16x2(D1[nt * 4 + 0] + bb.x, D1[nt * 4 + 1] + bb.y);
            dltp[2 * nt + 1] = pack_f16x2(D1[nt * 4 + 2] + bb.x, D1[nt * 4 + 3] + bb.y);
        }

        // epi-b: h2 = relu(Dx) -> A frags
#pragma unroll
        for (int nt = 0; nt < 8; nt++) {
            int kt = nt >> 1, half = nt & 1, slot = kt * 4 + 2 * half;
            Au[slot]     = pack_f16x2(fmaxf(Dx[nt * 4 + 0], 0.f), fmaxf(Dx[nt * 4 + 1], 0.f));
            Au[slot + 1] = pack_f16x2(fmaxf(Dx[nt * 4 + 2], 0.f), fmaxf(Dx[nt * 4 + 3], 0.f));
        }

        // v gathers (covered by G3)
        uint4 v0a = __ldg((const uint4*)(g_vh + sn[0] * 64 + 16 * t));
        uint4 v0b = __ldg((const uint4*)(g_vh + sn[0] * 64 + 16 * t + 8));
        uint4 v1a = __ldg((const uint4*)(g_vh + sn[1] * 64 + 16 * t));
        uint4 v1b = __ldg((const uint4*)(g_vh + sn[1] * 64 + 16 * t + 8));

        // G3: logits = h2 @ Wa2
#pragma unroll
        for (int i = 0; i < 32; i++) Dx[i] = 0.f;
        gemm1p(Dx, Au, bfA2h, lane);

        // final epi with 2-level hierarchical dst-merge
        uint32_t wv0[8] = {v0a.x, v0a.y, v0a.z, v0a.w, v0b.x, v0b.y, v0b.z, v0b.w};
        uint32_t wv1[8] = {v1a.x, v1a.y, v1a.z, v1a.w, v1b.x, v1b.y, v1b.z, v1b.w};
        float* sp_ = (float*)g_s4;
        float* ap_ = (float*)g_acc4;
        float ms[16], ma[16];
#pragma unroll
        for (int ntp = 0; ntp < 4; ntp++) {
            int na = 2 * ntp, nb = na + 1;
            float2 ba_a = sBa2[4 * na + t], ba_b = sBa2[4 * nb + t];
            float2 va0 = h2f2(wv0[na]), vb0 = h2f2(wv0[nb]);
            float2 va1 = h2f2(wv1[na]), vb1 = h2f2(wv1[nb]);
            float2 dna0 = h2f2(dltp[2 * na]),     dnb0 = h2f2(dltp[2 * nb]);
            float2 dna1 = h2f2(dltp[2 * na + 1]), dnb1 = h2f2(dltp[2 * nb + 1]);
            float e00 = __expf(Dx[na * 4 + 0] + ba_a.x);
            float e01 = __expf(Dx[na * 4 + 1] + ba_a.y);
            float e02 = __expf(Dx[nb * 4 + 0] + ba_b.x);
            float e03 = __expf(Dx[nb * 4 + 1] + ba_b.y);
            float a00 = e00 * (va0.x + dna0.x);
            float a01 = e01 * (va0.y + dna0.y);
            float a02 = e02 * (vb0.x + dnb0.x);
            float a03 = e03 * (vb0.y + dnb0.y);
            float e10 = __expf(Dx[na * 4 + 2] + ba_a.x);
            float e11 = __expf(Dx[na * 4 + 3] + ba_a.y);
            float e12 = __expf(Dx[nb * 4 + 2] + ba_b.x);
            float e13 = __expf(Dx[nb * 4 + 3] + ba_b.y);
            float a10 = e10 * (va1.x + dna1.x);
            float a11 = e11 * (va1.y + dna1.y);
            float a12 = e12 * (vb1.x + dnb1.x);
            float a13 = e13 * (vb1.y + dnb1.y);
            if (m01) {
                ms[4*ntp+0] = e00 + e10; ms[4*ntp+1] = e01 + e11;
                ms[4*ntp+2] = e02 + e12; ms[4*ntp+3] = e03 + e13;
                ma[4*ntp+0] = a00 + a10; ma[4*ntp+1] = a01 + a11;
                ma[4*ntp+2] = a02 + a12; ma[4*ntp+3] = a03 + a13;
            } else {
                ms[4*ntp+0] = e00; ms[4*ntp+1] = e01;
                ms[4*ntp+2] = e02; ms[4*ntp+3] = e03;
                ma[4*ntp+0] = a00; ma[4*ntp+1] = a01;
                ma[4*ntp+2] = a02; ma[4*ntp+3] = a03;
                int off1 = dn[1] * 64 + 16 * t + 4 * ntp;
                red4((float4*)(sp_ + off1), e10, e11, e12, e13);
                red4((float4*)(ap_ + off1), a10, a11, a12, a13);
            }
        }
        // level 1: xor-4 (merge 4 consecutive edges)
        unsigned bal = __ballot_sync(0xffffffffu, m01);
        bool pm01 = (bal >> (lane ^ 4)) & 1u;
        int pdn0 = __shfl_xor_sync(0xffffffffu, dn[0], 4);
        bool joint  = m01 && pm01 && (dn[0] == pdn0);
        bool absorb = joint && ((g & 1) == 0);
        bool dead   = joint && ((g & 1) == 1);
#pragma unroll
        for (int i = 0; i < 16; i++) {
            float pv = __shfl_xor_sync(0xffffffffu, ms[i], 4);
            if (absorb) ms[i] += pv;
        }
#pragma unroll
        for (int i = 0; i < 16; i++) {
            float pv = __shfl_xor_sync(0xffffffffu, ma[i], 4);
            if (absorb) ma[i] += pv;
        }
        // level 2: xor-8 (merge 8 consecutive edges)
        unsigned bal4 = __ballot_sync(0xffffffffu, joint);
        bool pjoint = (bal4 >> (lane ^ 8)) & 1u;
        int p8dn = __shfl_xor_sync(0xffffffffu, dn[0], 8);
        bool joint8  = joint && pjoint && (dn[0] == p8dn);
        bool absorb8 = joint8 && ((g & 2) == 0);
        bool dead8   = joint8 && ((g & 2) != 0);
#pragma unroll
        for (int i = 0; i < 16; i++) {
            float pv = __shfl_xor_sync(0xffffffffu, ms[i], 8);
            if (absorb8) ms[i] += pv;
        }
#pragma unroll
        for (int i = 0; i < 16; i++) {
            float pv = __shfl_xor_sync(0xffffffffu, ma[i], 8);
            if (absorb8) ma[i] += pv;
        }
        if (!dead && !dead8) {
            int off0 = dn[0] * 64 + 16 * t;
#pragma unroll
            for (int q = 0; q < 4; q++) {
                red4((float4*)(sp_ + off0 + 4 * q), ms[4*q], ms[4*q+1], ms[4*q+2], ms[4*q+3]);
                red4((float4*)(ap_ + off0 + 4 * q), ma[4*q], ma[4*q+1], ma[4*q+2], ma[4*q+3]);
            }
        }
    }
}

// ---------------- kernel 3: normalize + lin_out + relu (mma) ----------------
__global__ __launch_bounds__(256) void node_out_kernel(
    const float* __restrict__ Wout, const float* __restrict__ bout,
    float* __restrict__ out)
{
    extern __shared__ __align__(16) char smem[];
    uint4*  sBF  = (uint4*)smem;                  // Wout hi + lo = 16KB
    float2* sB   = (float2*)(smem + 16384);
    const int tid = threadIdx.x;
    build_bf4(sBF, sBF + 512, Wout, tid, 256);
    if (tid < 32) sB[tid] = make_float2(bout[2 * tid], bout[2 * tid + 1]);
    __syncthreads();

    const int lane = tid & 31;
    const int g = lane >> 2, t = lane & 3;
    const float* accp = (const float*)g_acc4;
    const float* ssp  = (const float*)g_s4;

    const int nTiles = Nn / 16;  // 3125
    const int wStride = gridDim.x * 8;
    for (int tile = blockIdx.x * 8 + (tid >> 5); tile < nTiles; tile += wStride) {
        const int n0 = tile * 16;

        float rg0[16], rg1[16];
#pragma unroll
        for (int q = 0; q < 4; q++) {
            float4 a0 = *(const float4*)(accp + (n0 + g) * 64 + 16 * t + 4 * q);
            float4 s0 = *(const float4*)(ssp  + (n0 + g) * 64 + 16 * t + 4 * q);
            rg0[4 * q + 0] = a0.x / (s0.x + 1e-16f);
            rg0[4 * q + 1] = a0.y / (s0.y + 1e-16f);
            rg0[4 * q + 2] = a0.z / (s0.z + 1e-16f);
            rg0[4 * q + 3] = a0.w / (s0.w + 1e-16f);
            float4 a1 = *(const float4*)(accp + (n0 + g + 8) * 64 + 16 * t + 4 * q);
            float4 s1 = *(const float4*)(ssp  + (n0 + g + 8) * 64 + 16 * t + 4 * q);
            rg1[4 * q + 0] = a1.x / (s1.x + 1e-16f);
            rg1[4 * q + 1] = a1.y / (s1.y + 1e-16f);
            rg1[4 * q + 2] = a1.z / (s1.z + 1e-16f);
            rg1[4 * q + 3] = a1.w / (s1.w + 1e-16f);
        }

        uint32_t Ah[16], Al[16];
#pragma unroll
        for (int nt = 0; nt < 8; nt++) {
            int kt = nt >> 1, half = nt & 1, slot = kt * 4 + 2 * half;
            pack_hl_f16(rg0[2 * nt], rg0[2 * nt + 1], Ah[slot],     Al[slot]);
            pack_hl_f16(rg1[2 * nt], rg1[2 * nt + 1], Ah[slot + 1], Al[slot + 1]);
        }

        float D[32];
#pragma unroll
        for (int i = 0; i < 32; i++) D[i] = 0.f;
        gemm3p(D, Ah, Al, sBF, sBF + 512, lane);

#pragma unroll
        for (int nt = 0; nt < 8; nt++) {
            int c0 = 8 * nt + 2 * t;
            float2 bb = sB[4 * nt + t];
            *(float2*)&out[(n0 + g    ) * 64 + c0] =
                make_float2(fmaxf(D[nt * 4 + 0] + bb.x, 0.f),
                            fmaxf(D[nt * 4 + 1] + bb.y, 0.f));
            *(float2*)&out[(n0 + g + 8) * 64 + c0] =
                make_float2(fmaxf(D[nt * 4 + 2] + bb.x, 0.f),
                            fmaxf(D[nt * 4 + 3] + bb.y, 0.f));
        }
    }
}

// ---------------- launch ----------------
extern "C" void kernel_launch(void* const* d_in, const int* in_sizes, int n_in,
                              void* d_out, int out_size)
{
    const float* x    = (const float*)d_in[0];
    const float* pos  = (const float*)d_in[1];
    const int*   ei   = (const int*)  d_in[2];
    const float* Win  = (const float*)d_in[3];
    const float* bin  = (const float*)d_in[4];
    const float* Wlin = (const float*)d_in[5];
    const float* Wsrc = (const float*)d_in[6];
    const float* Wdst = (const float*)d_in[7];
    const float* Wp1  = (const float*)d_in[8];
    const float* bp1  = (const float*)d_in[9];
    const float* Wp2  = (const float*)d_in[10];
    const float* bp2  = (const float*)d_in[11];
    const float* Wa1  = (const float*)d_in[12];
    const float* ba1  = (const float*)d_in[13];
    const float* Wa2  = (const float*)d_in[14];
    const float* ba2  = (const float*)d_in[15];
    const float* Wout = (const float*)d_in[16];
    const float* bout = (const float*)d_in[17];

    const int projSmem = 65536 + 256;
    const int outSmem  = 16384 + 256;
    cudaFuncSetAttribute(node_proj_kernel,  cudaFuncAttributeMaxDynamicSharedMemorySize, projSmem);
    cudaFuncSetAttribute(edge_fused_kernel, cudaFuncAttributeMaxDynamicSharedMemorySize, ESM_TOTAL);
    cudaFuncSetAttribute(node_out_kernel,   cudaFuncAttributeMaxDynamicSharedMemorySize, outSmem);

    zero_cnt_kernel<<<(Nn + 255) / 256, 256>>>();
    init_hist_kernel<<<Ee / 256, 256>>>(ei);
    scanA_kernel<<<(Nn + 1023) / 1024, 1024>>>();
    scatter_kernel<<<(Ee / 4 + 255) / 256, 256>>>(ei);
    fold_kernel<<<48, 256>>>(Wsrc, Wdst, Wp2, Wa1, bp2, ba1);
    node_proj_kernel<<<782, 256, projSmem>>>(x, Win, bin, Wlin);
    edge_fused_kernel<<<296, 256, ESM_TOTAL>>>(pos, Wp1, bp1, Wp2, bp2, Wa2, ba2);
    node_out_kernel<<<782, 256, outSmem>>>(Wout, bout, (float*)d_out);
}

// round 16
// speedup vs baseline: 1.2014x; 1.0241x over previous
#include <cuda_runtime.h>
#include <cuda_fp16.h>
#include <cstdint>
#include <cstddef>

#define Nn 50000
#define Ee 800000

// ---------------- scratch (static device globals; no allocation) ----------------
__device__ float4 g_s4  [Nn * 16];
__device__ float4 g_acc4[Nn * 16];
__device__ __align__(16) __half g_vh[Nn * 64];
__device__ __align__(16) __half g_Qh[Nn * 64];
__device__ __align__(16) __half g_Ph[Nn * 64];
__device__ float g_WsA[4096];
__device__ float g_WdA[4096];
__device__ float g_WpA[4096];
__device__ float g_cvec[64];
// dst-sort machinery
__device__ int  g_binCnt[Nn];
__device__ int  g_binCur[Nn];
__device__ int  g_blkSum[64];
__device__ int2 g_esd[Ee];     // sorted (src,dst) records

// ---------------- helpers ----------------
__device__ __forceinline__ uint32_t pack_f16x2(float a, float b) {
    uint32_t w;
    asm("cvt.rn.f16x2.f32 %0, %1, %2;" : "=r"(w) : "f"(b), "f"(a));  // lo=a, hi=b
    return w;
}
__device__ __forceinline__ void pack_hl_f16(float a, float b, uint32_t& h, uint32_t& l) {
    asm("cvt.rn.f16x2.f32 %0, %1, %2;" : "=r"(h) : "f"(b), "f"(a));
    __half2 h2 = *reinterpret_cast<__half2*>(&h);
    float la = a - __half2float(h2.x);
    float lb = b - __half2float(h2.y);
    asm("cvt.rn.f16x2.f32 %0, %1, %2;" : "=r"(l) : "f"(lb), "f"(la));
}
__device__ __forceinline__ float2 h2f2(uint32_t w) {
    __half2 h = *reinterpret_cast<__half2*>(&w);
    return make_float2(__half2float(h.x), __half2float(h.y));
}
__device__ __forceinline__ void red4(float4* p, float a, float b, float c, float d) {
    asm volatile("red.global.add.v4.f32 [%0], {%1, %2, %3, %4};"
                 :: "l"(p), "f"(a), "f"(b), "f"(c), "f"(d) : "memory");
}
__device__ __forceinline__ void mma_f16(float* d, const uint32_t* a, uint32_t b0, uint32_t b1) {
    asm volatile(
        "mma.sync.aligned.m16n8k16.row.col.f32.f16.f16.f32 "
        "{%0,%1,%2,%3},{%4,%5,%6,%7},{%8,%9},{%0,%1,%2,%3};"
        : "+f"(d[0]), "+f"(d[1]), "+f"(d[2]), "+f"(d[3])
        : "r"(a[0]), "r"(a[1]), "r"(a[2]), "r"(a[3]), "r"(b0), "r"(b1));
}
__device__ __forceinline__ void gemm1p(float* D, const uint32_t* Ah,
                                       const uint4* __restrict__ bf, int lane) {
#pragma unroll
    for (int kt = 0; kt < 4; kt++)
#pragma unroll
        for (int ntp = 0; ntp < 4; ntp++) {
            uint4 b = bf[(kt * 4 + ntp) * 32 + lane];
            mma_f16(D + (2 * ntp)     * 4, Ah + kt * 4, b.x, b.y);
            mma_f16(D + (2 * ntp + 1) * 4, Ah + kt * 4, b.z, b.w);
        }
}
__device__ __forceinline__ void gemm2p(float* D, const uint32_t* Ah,
                                       const uint4* __restrict__ bfH,
                                       const uint4* __restrict__ bfL, int lane) {
#pragma unroll
    for (int kt = 0; kt < 4; kt++)
#pragma unroll
        for (int ntp = 0; ntp < 4; ntp++) {
            uint4 bh = bfH[(kt * 4 + ntp) * 32 + lane];
            mma_f16(D + (2 * ntp)     * 4, Ah + kt * 4, bh.x, bh.y);
            mma_f16(D + (2 * ntp + 1) * 4, Ah + kt * 4, bh.z, bh.w);
            uint4 bl = bfL[(kt * 4 + ntp) * 32 + lane];
            mma_f16(D + (2 * ntp)     * 4, Ah + kt * 4, bl.x, bl.y);
            mma_f16(D + (2 * ntp + 1) * 4, Ah + kt * 4, bl.z, bl.w);
        }
}
__device__ __forceinline__ void gemm3p(float* D, const uint32_t* Ah, const uint32_t* Al,
                                       const uint4* __restrict__ bfH,
                                       const uint4* __restrict__ bfL, int lane) {
#pragma unroll
    for (int kt = 0; kt < 4; kt++)
#pragma unroll
        for (int ntp = 0; ntp < 4; ntp++) {
            uint4 bh = bfH[(kt * 4 + ntp) * 32 + lane];
            mma_f16(D + (2 * ntp)     * 4, Ah + kt * 4, bh.x, bh.y);
            mma_f16(D + (2 * ntp + 1) * 4, Ah + kt * 4, bh.z, bh.w);
            mma_f16(D + (2 * ntp)     * 4, Al + kt * 4, bh.x, bh.y);
            mma_f16(D + (2 * ntp + 1) * 4, Al + kt * 4, bh.z, bh.w);
            uint4 bl = bfL[(kt * 4 + ntp) * 32 + lane];
            mma_f16(D + (2 * ntp)     * 4, Ah + kt * 4, bl.x, bl.y);
            mma_f16(D + (2 * ntp + 1) * 4, Ah + kt * 4, bl.z, bl.w);
        }
}

__device__ __forceinline__ void build_bf4(uint4* dstH, uint4* dstL,
                                          const float* __restrict__ W,
                                          int tid, int nth) {
    for (int i = tid; i < 1024; i += nth) {
        int kt = i >> 8, nt = (i >> 5) & 7, lane = i & 31;
        int g = lane >> 2, t = lane & 3;
        int col = 8 * nt + g;
        int k0  = 16 * kt + 2 * t;
        float w00 = W[(k0    ) * 64 + col];
        float w01 = W[(k0 + 1) * 64 + col];
        float w10 = W[(k0 + 8) * 64 + col];
        float w11 = W[(k0 + 9) * 64 + col];
        uint32_t h0, l0, h1, l1;
        pack_hl_f16(w00, w01, h0, l0);
        pack_hl_f16(w10, w11, h1, l1);
        uint32_t* pH = (uint32_t*)&dstH[(kt * 4 + (nt >> 1)) * 32 + lane];
        int sub = (nt & 1) * 2;
        pH[sub] = h0; pH[sub + 1] = h1;
        if (dstL) {
            uint32_t* pL = (uint32_t*)&dstL[(kt * 4 + (nt >> 1)) * 32 + lane];
            pL[sub] = l0; pL[sub + 1] = l1;
        }
    }
}

// ---------------- kernel -1: fold weight products (fp32) ----------------
__global__ __launch_bounds__(256) void fold_kernel(
    const float* __restrict__ Wsrc, const float* __restrict__ Wdst,
    const float* __restrict__ Wp2,  const float* __restrict__ Wa1,
    const float* __restrict__ bp2,  const float* __restrict__ ba1)
{
    int gid = blockIdx.x * blockDim.x + threadIdx.x;
    if (gid < 3 * 4096) {
        int m = gid >> 12;
        int idx = gid & 4095;
        int i = idx >> 6, j = idx & 63;
        const float* A = (m == 0) ? Wsrc : (m == 1) ? Wdst : Wp2;
        float s = 0.f;
        for (int k = 0; k < 64; k++) s = fmaf(A[i * 64 + k], Wa1[k * 64 + j], s);
        float* O = (m == 0) ? g_WsA : (m == 1) ? g_WdA : g_WpA;
        O[idx] = s;
    }
    if (gid < 64) {
        float s = ba1[gid];
        for (int k = 0; k < 64; k++) s = fmaf(bp2[k], Wa1[k * 64 + gid], s);
        g_cvec[gid] = s;
    }
}

// ---------------- kernel 0a: zero histogram bins ----------------
__global__ __launch_bounds__(256) void zero_cnt_kernel() {
    int i = blockIdx.x * blockDim.x + threadIdx.x;
    if (i < Nn) g_binCnt[i] = 0;
}

// ---------------- kernel 0b: zero accumulators + dst histogram (Nn*16 == Ee) ----------------
__global__ __launch_bounds__(256) void init_hist_kernel(const int* __restrict__ ei) {
    int i = blockIdx.x * blockDim.x + threadIdx.x;   // grid covers exactly 800000
    g_s4[i]   = make_float4(0.f, 0.f, 0.f, 0.f);
    g_acc4[i] = make_float4(0.f, 0.f, 0.f, 0.f);
    atomicAdd(&g_binCnt[ei[Ee + i]], 1);
}

// block-local exclusive scan over 1024 bins; block total to g_blkSum
__global__ __launch_bounds__(1024) void scanA_kernel() {
    __shared__ int wsum[32];
    int i = blockIdx.x * 1024 + threadIdx.x;
    int lane = threadIdx.x & 31, wid = threadIdx.x >> 5;
    int v = (i < Nn) ? g_binCnt[i] : 0;
    int incl = v;
#pragma unroll
    for (int o = 1; o < 32; o <<= 1) {
        int u = __shfl_up_sync(0xffffffffu, incl, o);
        if (lane >= o) incl += u;
    }
    if (lane == 31) wsum[wid] = incl;
    __syncthreads();
    if (wid == 0) {
        int w = wsum[lane];
        int wi = w;
#pragma unroll
        for (int o = 1; o < 32; o <<= 1) {
            int u = __shfl_up_sync(0xffffffffu, wi, o);
            if (lane >= o) wi += u;
        }
        wsum[lane] = wi - w;
    }
    __syncthreads();
    int excl = incl - v + wsum[wid];
    if (i < Nn) g_binCur[i] = excl;
    if (threadIdx.x == 1023) g_blkSum[blockIdx.x] = excl + v;
}

// ILP-8 scatter; each block re-derives the 49-entry block-offset prefix itself
__global__ __launch_bounds__(256) void scatter_kernel(const int* __restrict__ ei) {
    __shared__ int sOff[64];
    const int nBlk = (Nn + 1023) / 1024;  // 49
    if (threadIdx.x < 32) {
        int lane = threadIdx.x;
        int a = (lane < nBlk) ? g_blkSum[lane] : 0;
        int b = (lane + 32 < nBlk) ? g_blkSum[lane + 32] : 0;
        int ia = a, ib = b;
#pragma unroll
        for (int o = 1; o < 32; o <<= 1) {
            int u = __shfl_up_sync(0xffffffffu, ia, o);
            if (lane >= o) ia += u;
            int u2 = __shfl_up_sync(0xffffffffu, ib, o);
            if (lane >= o) ib += u2;
        }
        int totA = __shfl_sync(0xffffffffu, ia, 31);
        sOff[lane]      = ia - a;
        sOff[lane + 32] = totA + ib - b;
    }
    __syncthreads();
    int base = (blockIdx.x * blockDim.x + threadIdx.x) * 8;
    if (base >= Ee) return;
    int4 sA = *(const int4*)(ei + base);
    int4 sB = *(const int4*)(ei + base + 4);
    int4 dA = *(const int4*)(ei + Ee + base);
    int4 dB = *(const int4*)(ei + Ee + base + 4);
    int ss[8] = {sA.x, sA.y, sA.z, sA.w, sB.x, sB.y, sB.z, sB.w};
    int dd[8] = {dA.x, dA.y, dA.z, dA.w, dB.x, dB.y, dB.z, dB.w};
#pragma unroll
    for (int j = 0; j < 8; j++) {
        int d = dd[j];
        int p = sOff[d >> 10] + atomicAdd(&g_binCur[d], 1);
        g_esd[p] = make_int2(ss[j], d);
    }
}

// ---------------- kernel 1: node projections ----------------
__global__ __launch_bounds__(256) void node_proj_kernel(
    const float* __restrict__ x,
    const float* __restrict__ Win,  const float* __restrict__ bin,
    const float* __restrict__ Wlin)
{
    extern __shared__ __align__(16) char smem[];
    uint4*  sBF  = (uint4*)smem;                       // 8 x 512 uint4 = 64KB
    float2* sBin = (float2*)(smem + 65536);
    const int tid = threadIdx.x;

    build_bf4(sBF + 0 * 512, sBF + 1 * 512, Win,  tid, 256);
    build_bf4(sBF + 2 * 512, sBF + 3 * 512, Wlin, tid, 256);
    build_bf4(sBF + 4 * 512, sBF + 5 * 512, (const float*)g_WsA, tid, 256);
    build_bf4(sBF + 6 * 512, sBF + 7 * 512, (const float*)g_WdA, tid, 256);
    if (tid < 32) sBin[tid] = make_float2(bin[2 * tid], bin[2 * tid + 1]);
    __syncthreads();

    const int lane = tid & 31;
    const int g = lane >> 2, t = lane & 3;

    __half* outs[3] = { g_vh, g_Qh, g_Ph };

    const int nTiles = Nn / 16;  // 3125
    const int wStride = gridDim.x * 8;
    for (int tile = blockIdx.x * 8 + (tid >> 5); tile < nTiles; tile += wStride) {
        const int n0 = tile * 16;

        uint32_t Ah[16];
#pragma unroll
        for (int kt = 0; kt < 4; kt++)
#pragma unroll
            for (int half = 0; half < 2; half++)
#pragma unroll
                for (int h = 0; h < 2; h++) {
                    float2 xx = *(const float2*)&x[(n0 + g + 8 * h) * 64 + 16 * kt + 2 * t + 8 * half];
                    Ah[kt * 4 + h + 2 * half] = pack_f16x2(xx.x, xx.y);
                }

        float D[32];
#pragma unroll
        for (int i = 0; i < 32; i++) D[i] = 0.f;
        gemm2p(D, Ah, sBF + 0 * 512, sBF + 1 * 512, lane);

        uint32_t Ah2[16];
#pragma unroll
        for (int nt = 0; nt < 8; nt++) {
            float2 bb = sBin[4 * nt + t];
            int kt = nt >> 1, half = nt & 1, slot = kt * 4 + 2 * half;
            Ah2[slot]     = pack_f16x2(fmaxf(D[nt * 4 + 0] + bb.x, 0.f),
                                       fmaxf(D[nt * 4 + 1] + bb.y, 0.f));
            Ah2[slot + 1] = pack_f16x2(fmaxf(D[nt * 4 + 2] + bb.x, 0.f),
                                       fmaxf(D[nt * 4 + 3] + bb.y, 0.f));
        }

#pragma unroll
        for (int m = 0; m < 3; m++) {
#pragma unroll
            for (int i = 0; i < 32; i++) D[i] = 0.f;
            gemm2p(D, Ah2, sBF + (2 + 2 * m) * 512, sBF + (3 + 2 * m) * 512, lane);
            __half* o = outs[m];
#pragma unroll
            for (int ntp = 0; ntp < 4; ntp++) {
                int na = 2 * ntp, nb = na + 1;
                uint2 r0 = make_uint2(pack_f16x2(D[na * 4 + 0], D[na * 4 + 1]),
                                      pack_f16x2(D[nb * 4 + 0], D[nb * 4 + 1]));
                uint2 r8 = make_uint2(pack_f16x2(D[na * 4 + 2], D[na * 4 + 3]),
                                      pack_f16x2(D[nb * 4 + 2], D[nb * 4 + 3]));
                *(uint2*)(o + (n0 + g    ) * 64 + 16 * t + 4 * ntp) = r0;
                *(uint2*)(o + (n0 + g + 8) * 64 + 16 * t + 4 * ntp) = r8;
            }
        }
    }
}

// ---------------- kernel 2: fused edge kernel (dst-sorted, 2-level merged scatter) ----------------
#define ESM_WP1   24576
#define ESM_BP2   25600
#define ESM_CV    25856
#define ESM_BA2   26112
#define ESM_TOTAL 26624

__global__ __launch_bounds__(256, 2) void edge_fused_kernel(
    const float* __restrict__ pos,
    const float* __restrict__ Wp1, const float* __restrict__ bp1,
    const float* __restrict__ Wp2, const float* __restrict__ bp2,
    const float* __restrict__ Wa2, const float* __restrict__ ba2)
{
    extern __shared__ __align__(16) char smem[];
    uint4*  sBF  = (uint4*)smem;
    float4* sWp1 = (float4*)(smem + ESM_WP1);
    float2* sBp2 = (float2*)(smem + ESM_BP2);
    float2* sCv  = (float2*)(smem + ESM_CV);
    float2* sBa2 = (float2*)(smem + ESM_BA2);

    const int tid = threadIdx.x;
    build_bf4(sBF + 0 * 512, (uint4*)0, Wp2,                 tid, 256);
    build_bf4(sBF + 1 * 512, (uint4*)0, (const float*)g_WpA, tid, 256);
    build_bf4(sBF + 2 * 512, (uint4*)0, Wa2,                 tid, 256);
    if (tid < 64)
        sWp1[tid] = make_float4(Wp1[tid], Wp1[64 + tid], Wp1[128 + tid], bp1[tid]);
    if (tid < 32) {
        sBp2[tid] = make_float2(bp2[2 * tid], bp2[2 * tid + 1]);
        sCv[tid]  = make_float2(g_cvec[2 * tid], g_cvec[2 * tid + 1]);
        sBa2[tid] = make_float2(ba2[2 * tid], ba2[2 * tid + 1]);
    }
    __syncthreads();

    const int lane = tid & 31;
    const int g = lane >> 2, t = lane & 3;

    const uint4* bfP2h = sBF + 0 * 512;
    const uint4* bfPAh = sBF + 1 * 512;
    const uint4* bfA2h = sBF + 2 * 512;

    const int nTiles = Ee / 16;          // 50000
    const int wStride = gridDim.x * 8;

    int tile = blockIdx.x * 8 + (tid >> 5);

    int pS = 0, pD = 0;
    float pr0 = 0.f, pr1 = 0.f, pr2 = 0.f;
    if (tile < nTiles && lane < 16) {
        int2 sd = __ldg(&g_esd[tile * 16 + lane]);
        pS = sd.x; pD = sd.y;
        pr0 = __ldg(&pos[pD * 3 + 0]) - __ldg(&pos[pS * 3 + 0]);
        pr1 = __ldg(&pos[pD * 3 + 1]) - __ldg(&pos[pS * 3 + 1]);
        pr2 = __ldg(&pos[pD * 3 + 2]) - __ldg(&pos[pS * 3 + 2]);
    }

    for (; tile < nTiles; tile += wStride) {
        // thread owns CONSECUTIVE sorted edges 2g (row g) and 2g+1 (row g+8)
        int sn[2], dn[2];
        float rl[2][3];
#pragma unroll
        for (int h = 0; h < 2; h++) {
            int src = 2 * g + h;
            sn[h]   = __shfl_sync(0xffffffffu, pS, src);
            dn[h]   = __shfl_sync(0xffffffffu, pD, src);
            rl[h][0] = __shfl_sync(0xffffffffu, pr0, src);
            rl[h][1] = __shfl_sync(0xffffffffu, pr1, src);
            rl[h][2] = __shfl_sync(0xffffffffu, pr2, src);
        }
        const bool m01 = (dn[0] == dn[1]);

        const int tn = tile + wStride;
        int nS = 0, nD = 0;
        if (tn < nTiles && lane < 16) {
            int2 sd = __ldg(&g_esd[tn * 16 + lane]);
            nS = sd.x; nD = sd.y;
        }

        // hoist P/Q gathers (consumed after G2'); reuse P when dn equal
        uint4 P0a = __ldg((const uint4*)(g_Ph + dn[0] * 64 + 16 * t));
        uint4 P0b = __ldg((const uint4*)(g_Ph + dn[0] * 64 + 16 * t + 8));
        uint4 Q0a = __ldg((const uint4*)(g_Qh + sn[0] * 64 + 16 * t));
        uint4 Q0b = __ldg((const uint4*)(g_Qh + sn[0] * 64 + 16 * t + 8));
        uint4 P1a, P1b;
        if (!m01) {
            P1a = __ldg((const uint4*)(g_Ph + dn[1] * 64 + 16 * t));
            P1b = __ldg((const uint4*)(g_Ph + dn[1] * 64 + 16 * t + 8));
        } else { P1a = P0a; P1b = P0b; }
        uint4 Q1a = __ldg((const uint4*)(g_Qh + sn[1] * 64 + 16 * t));
        uint4 Q1b = __ldg((const uint4*)(g_Qh + sn[1] * 64 + 16 * t + 8));

        // stage 1: u = relu(rel @ Wp1 + bp1) -> A frags
        uint32_t Au[16];
#pragma unroll
        for (int kt = 0; kt < 4; kt++)
#pragma unroll
            for (int half = 0; half < 2; half++) {
                int c0 = 16 * kt + 2 * t + 8 * half;
                float4 w0 = sWp1[c0];
                float4 w1 = sWp1[c0 + 1];
#pragma unroll
                for (int h = 0; h < 2; h++) {
                    float u0 = fmaxf(fmaf(rl[h][2], w0.z, fmaf(rl[h][1], w0.y,
                               fmaf(rl[h][0], w0.x, w0.w))), 0.f);
                    float u1 = fmaxf(fmaf(rl[h][2], w1.z, fmaf(rl[h][1], w1.y,
                               fmaf(rl[h][0], w1.x, w1.w))), 0.f);
                    Au[kt * 4 + h + 2 * half] = pack_f16x2(u0, u1);
                }
            }

        // G2': h2_pre = u @ WpA
        float Dx[32];
#pragma unroll
        for (int i = 0; i < 32; i++) Dx[i] = 0.f;
        gemm1p(Dx, Au, bfPAh, lane);

        if (tn < nTiles && lane < 16) {
            pr0 = __ldg(&pos[nD * 3 + 0]) - __ldg(&pos[nS * 3 + 0]);
            pr1 = __ldg(&pos[nD * 3 + 1]) - __ldg(&pos[nS * 3 + 1]);
            pr2 = __ldg(&pos[nD * 3 + 2]) - __ldg(&pos[nS * 3 + 2]);
        }
        pS = nS; pD = nD;

        // epi-a: Dx += cvec + P[dn] - Q[sn]
        {
            uint32_t wP0[8] = {P0a.x, P0a.y, P0a.z, P0a.w, P0b.x, P0b.y, P0b.z, P0b.w};
            uint32_t wQ0[8] = {Q0a.x, Q0a.y, Q0a.z, Q0a.w, Q0b.x, Q0b.y, Q0b.z, Q0b.w};
            uint32_t wP1[8] = {P1a.x, P1a.y, P1a.z, P1a.w, P1b.x, P1b.y, P1b.z, P1b.w};
            uint32_t wQ1[8] = {Q1a.x, Q1a.y, Q1a.z, Q1a.w, Q1b.x, Q1b.y, Q1b.z, Q1b.w};
#pragma unroll
            for (int nt = 0; nt < 8; nt++) {
                float2 cv = sCv[4 * nt + t];
                float2 p0 = h2f2(wP0[nt]), q0 = h2f2(wQ0[nt]);
                float2 p1 = h2f2(wP1[nt]), q1 = h2f2(wQ1[nt]);
                Dx[nt * 4 + 0] += cv.x + p0.x - q0.x;
                Dx[nt * 4 + 1] += cv.y + p0.y - q0.y;
                Dx[nt * 4 + 2] += cv.x + p1.x - q1.x;
                Dx[nt * 4 + 3] += cv.y + p1.y - q1.y;
            }
        }

        // G1: delta_raw = u @ Wp2 (latency filler)
        float D1[32];
#pragma unroll
        for (int i = 0; i < 32; i++) D1[i] = 0.f;
        gemm1p(D1, Au, bfP2h, lane);

        uint32_t dltp[16];
#pragma unroll
        for (int nt = 0; nt < 8; nt++) {
            float2 bb = sBp2[4 * nt + t];
            dltp[2 * nt]     = pack_f16x2(D1[nt * 4 + 0] + bb.x, D1[nt * 4 + 1] + bb.y);
            dltp[2 * nt + 1] = pack_f16x2(D1[nt * 4 + 2] + bb.x, D1[nt * 4 + 3] + bb.y);
        }

        // epi-b: h2 = relu(Dx) -> A frags
#pragma unroll
        for (int nt = 0; nt < 8; nt++) {
            int kt = nt >> 1, half = nt & 1, slot = kt * 4 + 2 * half;
            Au[slot]     = pack_f16x2(fmaxf(Dx[nt * 4 + 0], 0.f), fmaxf(Dx[nt * 4 + 1], 0.f));
            Au[slot + 1] = pack_f16x2(fmaxf(Dx[nt * 4 + 2], 0.f), fmaxf(Dx[nt * 4 + 3], 0.f));
        }

        // v gathers (covered by G3)
        uint4 v0a = __ldg((const uint4*)(g_vh + sn[0] * 64 + 16 * t));
        uint4 v0b = __ldg((const uint4*)(g_vh + sn[0] * 64 + 16 * t + 8));
        uint4 v1a = __ldg((const uint4*)(g_vh + sn[1] * 64 + 16 * t));
        uint4 v1b = __ldg((const uint4*)(g_vh + sn[1] * 64 + 16 * t + 8));

        // G3: logits = h2 @ Wa2
#pragma unroll
        for (int i = 0; i < 32; i++) Dx[i] = 0.f;
        gemm1p(Dx, Au, bfA2h, lane);

        // final epi with 2-level hierarchical dst-merge
        uint32_t wv0[8] = {v0a.x, v0a.y, v0a.z, v0a.w, v0b.x, v0b.y, v0b.z, v0b.w};
        uint32_t wv1[8] = {v1a.x, v1a.y, v1a.z, v1a.w, v1b.x, v1b.y, v1b.z, v1b.w};
        float* sp_ = (float*)g_s4;
        float* ap_ = (float*)g_acc4;
        float ms[16], ma[16];
#pragma unroll
        for (int ntp = 0; ntp < 4; ntp++) {
            int na = 2 * ntp, nb = na + 1;
            float2 ba_a = sBa2[4 * na + t], ba_b = sBa2[4 * nb + t];
            float2 va0 = h2f2(wv0[na]), vb0 = h2f2(wv0[nb]);
            float2 va1 = h2f2(wv1[na]), vb1 = h2f2(wv1[nb]);
            float2 dna0 = h2f2(dltp[2 * na]),     dnb0 = h2f2(dltp[2 * nb]);
            float2 dna1 = h2f2(dltp[2 * na + 1]), dnb1 = h2f2(dltp[2 * nb + 1]);
            float e00 = __expf(Dx[na * 4 + 0] + ba_a.x);
            float e01 = __expf(Dx[na * 4 + 1] + ba_a.y);
            float e02 = __expf(Dx[nb * 4 + 0] + ba_b.x);
            float e03 = __expf(Dx[nb * 4 + 1] + ba_b.y);
            float a00 = e00 * (va0.x + dna0.x);
            float a01 = e01 * (va0.y + dna0.y);
            float a02 = e02 * (vb0.x + dnb0.x);
            float a03 = e03 * (vb0.y + dnb0.y);
            float e10 = __expf(Dx[na * 4 + 2] + ba_a.x);
            float e11 = __expf(Dx[na * 4 + 3] + ba_a.y);
            float e12 = __expf(Dx[nb * 4 + 2] + ba_b.x);
            float e13 = __expf(Dx[nb * 4 + 3] + ba_b.y);
            float a10 = e10 * (va1.x + dna1.x);
            float a11 = e11 * (va1.y + dna1.y);
            float a12 = e12 * (vb1.x + dnb1.x);
            float a13 = e13 * (vb1.y + dnb1.y);
            if (m01) {
                ms[4*ntp+0] = e00 + e10; ms[4*ntp+1] = e01 + e11;
                ms[4*ntp+2] = e02 + e12; ms[4*ntp+3] = e03 + e13;
                ma[4*ntp+0] = a00 + a10; ma[4*ntp+1] = a01 + a11;
                ma[4*ntp+2] = a02 + a12; ma[4*ntp+3] = a03 + a13;
            } else {
                ms[4*ntp+0] = e00; ms[4*ntp+1] = e01;
                ms[4*ntp+2] = e02; ms[4*ntp+3] = e03;
                ma[4*ntp+0] = a00; ma[4*ntp+1] = a01;
                ma[4*ntp+2] = a02; ma[4*ntp+3] = a03;
                int off1 = dn[1] * 64 + 16 * t + 4 * ntp;
                red4((float4*)(sp_ + off1), e10, e11, e12, e13);
                red4((float4*)(ap_ + off1), a10, a11, a12, a13);
            }
        }
        // level 1: xor-4 (merge 4 consecutive edges)
        unsigned bal = __ballot_sync(0xffffffffu, m01);
        bool pm01 = (bal >> (lane ^ 4)) & 1u;
        int pdn0 = __shfl_xor_sync(0xffffffffu, dn[0], 4);
        bool joint  = m01 && pm01 && (dn[0] == pdn0);
        bool absorb = joint && ((g & 1) == 0);
        bool dead   = joint && ((g & 1) == 1);
#pragma unroll
        for (int i = 0; i < 16; i++) {
            float pv = __shfl_xor_sync(0xffffffffu, ms[i], 4);
            if (absorb) ms[i] += pv;
        }
#pragma unroll
        for (int i = 0; i < 16; i++) {
            float pv = __shfl_xor_sync(0xffffffffu, ma[i], 4);
            if (absorb) ma[i] += pv;
        }
        // level 2: xor-8 (merge 8 consecutive edges)
        unsigned bal4 = __ballot_sync(0xffffffffu, joint);
        bool pjoint = (bal4 >> (lane ^ 8)) & 1u;
        int p8dn = __shfl_xor_sync(0xffffffffu, dn[0], 8);
        bool joint8  = joint && pjoint && (dn[0] == p8dn);
        bool absorb8 = joint8 && ((g & 2) == 0);
        bool dead8   = joint8 && ((g & 2) != 0);
#pragma unroll
        for (int i = 0; i < 16; i++) {
            float pv = __shfl_xor_sync(0xffffffffu, ms[i], 8);
            if (absorb8) ms[i] += pv;
        }
#pragma unroll
        for (int i = 0; i < 16; i++) {
            float pv = __shfl_xor_sync(0xffffffffu, ma[i], 8);
            if (absorb8) ma[i] += pv;
        }
        if (!dead && !dead8) {
            int off0 = dn[0] * 64 + 16 * t;
#pragma unroll
            for (int q = 0; q < 4; q++) {
                red4((float4*)(sp_ + off0 + 4 * q), ms[4*q], ms[4*q+1], ms[4*q+2], ms[4*q+3]);
                red4((float4*)(ap_ + off0 + 4 * q), ma[4*q], ma[4*q+1], ma[4*q+2], ma[4*q+3]);
            }
        }
    }
}

// ---------------- kernel 3: normalize + lin_out + relu (mma) ----------------
__global__ __launch_bounds__(256) void node_out_kernel(
    const float* __restrict__ Wout, const float* __restrict__ bout,
    float* __restrict__ out)
{
    extern __shared__ __align__(16) char smem[];
    uint4*  sBF  = (uint4*)smem;                  // Wout hi + lo = 16KB
    float2* sB   = (float2*)(smem + 16384);
    const int tid = threadIdx.x;
    build_bf4(sBF, sBF + 512, Wout, tid, 256);
    if (tid < 32) sB[tid] = make_float2(bout[2 * tid], bout[2 * tid + 1]);
    __syncthreads();

    const int lane = tid & 31;
    const int g = lane >> 2, t = lane & 3;
    const float* accp = (const float*)g_acc4;
    const float* ssp  = (const float*)g_s4;

    const int nTiles = Nn / 16;  // 3125
    const int wStride = gridDim.x * 8;
    for (int tile = blockIdx.x * 8 + (tid >> 5); tile < nTiles; tile += wStride) {
        const int n0 = tile * 16;

        float rg0[16], rg1[16];
#pragma unroll
        for (int q = 0; q < 4; q++) {
            float4 a0 = *(const float4*)(accp + (n0 + g) * 64 + 16 * t + 4 * q);
            float4 s0 = *(const float4*)(ssp  + (n0 + g) * 64 + 16 * t + 4 * q);
            rg0[4 * q + 0] = a0.x / (s0.x + 1e-16f);
            rg0[4 * q + 1] = a0.y / (s0.y + 1e-16f);
            rg0[4 * q + 2] = a0.z / (s0.z + 1e-16f);
            rg0[4 * q + 3] = a0.w / (s0.w + 1e-16f);
            float4 a1 = *(const float4*)(accp + (n0 + g + 8) * 64 + 16 * t + 4 * q);
            float4 s1 = *(const float4*)(ssp  + (n0 + g + 8) * 64 + 16 * t + 4 * q);
            rg1[4 * q + 0] = a1.x / (s1.x + 1e-16f);
            rg1[4 * q + 1] = a1.y / (s1.y + 1e-16f);
            rg1[4 * q + 2] = a1.z / (s1.z + 1e-16f);
            rg1[4 * q + 3] = a1.w / (s1.w + 1e-16f);
        }

        uint32_t Ah[16], Al[16];
#pragma unroll
        for (int nt = 0; nt < 8; nt++) {
            int kt = nt >> 1, half = nt & 1, slot = kt * 4 + 2 * half;
            pack_hl_f16(rg0[2 * nt], rg0[2 * nt + 1], Ah[slot],     Al[slot]);
            pack_hl_f16(rg1[2 * nt], rg1[2 * nt + 1], Ah[slot + 1], Al[slot + 1]);
        }

        float D[32];
#pragma unroll
        for (int i = 0; i < 32; i++) D[i] = 0.f;
        gemm3p(D, Ah, Al, sBF, sBF + 512, lane);

#pragma unroll
        for (int nt = 0; nt < 8; nt++) {
            int c0 = 8 * nt + 2 * t;
            float2 bb = sB[4 * nt + t];
            *(float2*)&out[(n0 + g    ) * 64 + c0] =
                make_float2(fmaxf(D[nt * 4 + 0] + bb.x, 0.f),
                            fmaxf(D[nt * 4 + 1] + bb.y, 0.f));
            *(float2*)&out[(n0 + g + 8) * 64 + c0] =
                make_float2(fmaxf(D[nt * 4 + 2] + bb.x, 0.f),
                            fmaxf(D[nt * 4 + 3] + bb.y, 0.f));
        }
    }
}

// ---------------- launch (two-stream fork/join for capture) ----------------
extern "C" void kernel_launch(void* const* d_in, const int* in_sizes, int n_in,
                              void* d_out, int out_size)
{
    const float* x    = (const float*)d_in[0];
    const float* pos  = (const float*)d_in[1];
    const int*   ei   = (const int*)  d_in[2];
    const float* Win  = (const float*)d_in[3];
    const float* bin  = (const float*)d_in[4];
    const float* Wlin = (const float*)d_in[5];
    const float* Wsrc = (const float*)d_in[6];
    const float* Wdst = (const float*)d_in[7];
    const float* Wp1  = (const float*)d_in[8];
    const float* bp1  = (const float*)d_in[9];
    const float* Wp2  = (const float*)d_in[10];
    const float* bp2  = (const float*)d_in[11];
    const float* Wa1  = (const float*)d_in[12];
    const float* ba1  = (const float*)d_in[13];
    const float* Wa2  = (const float*)d_in[14];
    const float* ba2  = (const float*)d_in[15];
    const float* Wout = (const float*)d_in[16];
    const float* bout = (const float*)d_in[17];

    const int projSmem = 65536 + 256;
    const int outSmem  = 16384 + 256;
    cudaFuncSetAttribute(node_proj_kernel,  cudaFuncAttributeMaxDynamicSharedMemorySize, projSmem);
    cudaFuncSetAttribute(edge_fused_kernel, cudaFuncAttributeMaxDynamicSharedMemorySize, ESM_TOTAL);
    cudaFuncSetAttribute(node_out_kernel,   cudaFuncAttributeMaxDynamicSharedMemorySize, outSmem);

    // fork a side stream for the (independent) sort chain
    cudaStream_t s2;
    cudaStreamCreateWithFlags(&s2, cudaStreamNonBlocking);
    cudaEvent_t evF, evJ;
    cudaEventCreateWithFlags(&evF, cudaEventDisableTiming);
    cudaEventCreateWithFlags(&evJ, cudaEventDisableTiming);

    cudaEventRecord(evF, 0);
    cudaStreamWaitEvent(s2, evF, 0);

    // branch A (s2): dst sort
    zero_cnt_kernel<<<(Nn + 255) / 256, 256, 0, s2>>>();
    init_hist_kernel<<<Ee / 256, 256, 0, s2>>>(ei);
    scanA_kernel<<<(Nn + 1023) / 1024, 1024, 0, s2>>>();
    scatter_kernel<<<(Ee / 8 + 255) / 256, 256, 0, s2>>>(ei);
    cudaEventRecord(evJ, s2);

    // branch B (main): fold + node projections
    fold_kernel<<<48, 256>>>(Wsrc, Wdst, Wp2, Wa1, bp2, ba1);
    node_proj_kernel<<<782, 256, projSmem>>>(x, Win, bin, Wlin);

    // join, then edge + output
    cudaStreamWaitEvent(0, evJ, 0);
    edge_fused_kernel<<<296, 256, ESM_TOTAL>>>(pos, Wp1, bp1, Wp2, bp2, Wa2, ba2);
    node_out_kernel<<<782, 256, outSmem>>>(Wout, bout, (float*)d_out);
}